// round 3
// baseline (speedup 1.0000x reference)
#include <cuda_runtime.h>
#include <cuda_bf16.h>
#include <math.h>

// Problem constants
#define NN 100000      // nodes
#define EE 800000      // directed edges
#define EF 16
#define HID 8
#define H1 8
#define C1 16
#define F1 (H1 * C1)   // 128
#define NC 16

// ---------------- scratch (device globals; no allocation allowed) -------------
__device__ __align__(16) float d_h0[NN * HID];        // NNConv accum -> h0
__device__ __align__(16) float d_hf1[NN * F1];        // GAT1 transformed features
__device__ __align__(16) float d_es1[NN * H1];
__device__ __align__(16) float d_ed1[NN * H1];
__device__ __align__(16) float d_o1[NN * F1];         // GAT1 output (pre-bias/ELU)
__device__ __align__(16) float d_hf2[NN * NC];        // GAT2 transformed features
__device__ __align__(16) float d_es2[NN];
__device__ __align__(16) float d_ed2[NN];
// CSR by destination
__device__ int d_deg[NN];
__device__ int d_rowptr[NN + 1];
__device__ int d_cur[NN];
__device__ int d_cidx[EE];     // src ids grouped by dst

__device__ __forceinline__ float lrelu(float v) { return v > 0.f ? v : 0.2f * v; }

// ---------------- zero accumulators ----------------
__global__ void zero_all() {
    int i = blockIdx.x * blockDim.x + threadIdx.x;
    if (i < NN * HID) d_h0[i] = 0.f;
    if (i < NN) d_deg[i] = 0;
}

// ---------------- NNConv edge pass: edge MLP + scatter (+ degree) ----------------
__global__ void nnconv_edge(const float* __restrict__ x,
                            const int* __restrict__ ei,
                            const float* __restrict__ ea,
                            const float* __restrict__ w1, const float* __restrict__ b1,
                            const float* __restrict__ w2, const float* __restrict__ b2) {
    __shared__ float sw1[EF * HID];
    __shared__ float sw2[HID * HID];
    __shared__ float sb1[HID];
    __shared__ float sb2[HID];
    int t = threadIdx.x;
    if (t < EF * HID) sw1[t] = w1[t];
    if (t < HID * HID) sw2[t] = w2[t];
    if (t < HID) { sb1[t] = b1[t]; sb2[t] = b2[t]; }
    __syncthreads();

    int e = blockIdx.x * blockDim.x + t;
    if (e >= EE) return;
    int s = ei[e];
    int d = ei[EE + e];

    float a[EF];
    const float4* ea4 = (const float4*)(ea) + e * 4;
#pragma unroll
    for (int j = 0; j < 4; j++) {
        float4 v = ea4[j];
        a[j * 4 + 0] = v.x; a[j * 4 + 1] = v.y; a[j * 4 + 2] = v.z; a[j * 4 + 3] = v.w;
    }

    float hm[HID];
#pragma unroll
    for (int k = 0; k < HID; k++) {
        float acc = sb1[k];
#pragma unroll
        for (int i = 0; i < EF; i++) acc = fmaf(a[i], sw1[i * HID + k], acc);
        hm[k] = fmaxf(acc, 0.f);
    }

    float xs = __ldg(&x[s]);
    float we[HID];
#pragma unroll
    for (int o = 0; o < HID; o++) {
        float acc = sb2[o];
#pragma unroll
        for (int k = 0; k < HID; k++) acc = fmaf(hm[k], sw2[k * HID + o], acc);
        we[o] = xs * acc;
    }
    float4* dst4 = (float4*)(&d_h0[d * HID]);
    atomicAdd(dst4 + 0, make_float4(we[0], we[1], we[2], we[3]));
    atomicAdd(dst4 + 1, make_float4(we[4], we[5], we[6], we[7]));
    atomicAdd(&d_deg[d], 1);
}

// ---------------- exclusive scan of degrees -> rowptr, cur ----------------
__global__ void scan_deg() {
    __shared__ int ssum[1024];
    const int T = 1024;
    const int CH = (NN + T - 1) / T;   // 98
    int t = threadIdx.x;
    int lo = t * CH;
    int hi = lo + CH; if (hi > NN) hi = NN;
    int sum = 0;
    for (int i = lo; i < hi; i++) sum += d_deg[i];
    ssum[t] = sum;
    __syncthreads();
    // Hillis-Steele inclusive scan
    for (int off = 1; off < T; off <<= 1) {
        int v = (t >= off) ? ssum[t - off] : 0;
        __syncthreads();
        ssum[t] += v;
        __syncthreads();
    }
    int run = (t == 0) ? 0 : ssum[t - 1];
    for (int i = lo; i < hi; i++) {
        d_rowptr[i] = run;
        d_cur[i] = run;
        run += d_deg[i];
    }
    if (t == T - 1) d_rowptr[NN] = EE;
}

// ---------------- scatter edges into CSR slots ----------------
__global__ void csr_scatter(const int* __restrict__ ei) {
    int e = blockIdx.x * blockDim.x + threadIdx.x;
    if (e >= EE) return;
    int s = ei[e];
    int d = ei[EE + e];
    int pos = atomicAdd(&d_cur[d], 1);
    d_cidx[pos] = s;
}

// ---------------- NNConv node pass: mean + root + relu ----------------
__global__ void nnconv_node(const float* __restrict__ x,
                            const float* __restrict__ root,
                            const float* __restrict__ nnb) {
    int n = blockIdx.x * blockDim.x + threadIdx.x;
    if (n >= NN) return;
    int dg = d_deg[n];
    float inv = 1.f / (float)(dg > 1 ? dg : 1);
    float xr = x[n];
#pragma unroll
    for (int o = 0; o < HID; o++) {
        float v = d_h0[n * HID + o] * inv + xr * __ldg(&root[o]) + __ldg(&nnb[o]);
        d_h0[n * HID + o] = fmaxf(v, 0.f);
    }
}

// ---------------- GAT1 transform: warp per node, coalesced ----------------
__global__ void gat1_feat(const float* __restrict__ g1W,
                          const float* __restrict__ g1as,
                          const float* __restrict__ g1ad) {
    int gid = blockIdx.x * blockDim.x + threadIdx.x;
    int n = gid >> 5;
    int lane = gid & 31;
    if (n >= NN) return;

    float hv = d_h0[n * HID + (lane & 7)];
    float h[HID];
#pragma unroll
    for (int k = 0; k < HID; k++) h[k] = __shfl_sync(0xffffffffu, hv, k);

    const float4* W4 = (const float4*)g1W;  // [8][32] float4
    float4 acc = make_float4(0.f, 0.f, 0.f, 0.f);
#pragma unroll
    for (int k = 0; k < HID; k++) {
        float4 w = __ldg(&W4[k * 32 + lane]);
        acc.x = fmaf(h[k], w.x, acc.x);
        acc.y = fmaf(h[k], w.y, acc.y);
        acc.z = fmaf(h[k], w.z, acc.z);
        acc.w = fmaf(h[k], w.w, acc.w);
    }
    ((float4*)d_hf1)[n * 32 + lane] = acc;

    float4 as4 = __ldg(&((const float4*)g1as)[lane]);
    float4 ad4 = __ldg(&((const float4*)g1ad)[lane]);
    float es = acc.x * as4.x + acc.y * as4.y + acc.z * as4.z + acc.w * as4.w;
    float ed = acc.x * ad4.x + acc.y * ad4.y + acc.z * ad4.z + acc.w * ad4.w;
    es += __shfl_xor_sync(0xffffffffu, es, 1);
    es += __shfl_xor_sync(0xffffffffu, es, 2);
    ed += __shfl_xor_sync(0xffffffffu, ed, 1);
    ed += __shfl_xor_sync(0xffffffffu, ed, 2);
    if ((lane & 3) == 0) {
        d_es1[n * H1 + (lane >> 2)] = es;
        d_ed1[n * H1 + (lane >> 2)] = ed;
    }
}

// ---------------- GAT1 aggregate: warp-per-node CSR gather ----------------
__global__ void gat1_gather() {
    int gid = blockIdx.x * blockDim.x + threadIdx.x;
    int n = gid >> 5;
    int lane = gid & 31;
    if (n >= NN) return;
    int hh = lane >> 2;

    float ed_n = d_ed1[n * H1 + hh];
    // self loop
    float w = __expf(lrelu(d_es1[n * H1 + hh] + ed_n));
    float4 v = ((const float4*)d_hf1)[n * 32 + lane];
    float ax = w * v.x, ay = w * v.y, az = w * v.z, aw = w * v.w;
    float wsum = w;

    int r0 = d_rowptr[n];
    int r1 = d_rowptr[n + 1];
    for (int r = r0; r < r1; r++) {
        int s = __ldg(&d_cidx[r]);
        float es = __ldg(&d_es1[s * H1 + hh]);
        float ww = __expf(lrelu(es + ed_n));
        float4 hv = __ldg(&((const float4*)d_hf1)[s * 32 + lane]);
        ax = fmaf(ww, hv.x, ax);
        ay = fmaf(ww, hv.y, ay);
        az = fmaf(ww, hv.z, az);
        aw = fmaf(ww, hv.w, aw);
        wsum += ww;
    }
    float inv = 1.f / wsum;
    ((float4*)d_o1)[n * 32 + lane] = make_float4(ax * inv, ay * inv, az * inv, aw * inv);
}

// ---------------- GAT1 epilogue (bias+ELU) + GAT2 transform: warp per node ----------------
__global__ void gat2_feat(const float* __restrict__ g1b,
                          const float* __restrict__ g2W,
                          const float* __restrict__ g2as,
                          const float* __restrict__ g2ad) {
    int gid = blockIdx.x * blockDim.x + threadIdx.x;
    int lane = gid & 31;
    int warp = gid >> 5;
    int nw = (gridDim.x * blockDim.x) >> 5;

    // lane owns input rows j = 4*lane .. 4*lane+3 of W2 [128][16]
    float w[4][NC];
#pragma unroll
    for (int q = 0; q < 4; q++)
#pragma unroll
        for (int c = 0; c < NC; c++)
            w[q][c] = __ldg(&g2W[(lane * 4 + q) * NC + c]);
    float4 b4 = __ldg(&((const float4*)g1b)[lane]);

    for (int n = warp; n < NN; n += nw) {
        float4 v4 = __ldg(&((const float4*)d_o1)[n * 32 + lane]);
        float v[4];
        v[0] = v4.x + b4.x; v[1] = v4.y + b4.y; v[2] = v4.z + b4.z; v[3] = v4.w + b4.w;
#pragma unroll
        for (int q = 0; q < 4; q++) v[q] = v[q] > 0.f ? v[q] : (__expf(v[q]) - 1.f);

        float acc[NC];
#pragma unroll
        for (int c = 0; c < NC; c++)
            acc[c] = v[0] * w[0][c] + v[1] * w[1][c] + v[2] * w[2][c] + v[3] * w[3][c];
        // butterfly: all lanes end with full sum
#pragma unroll
        for (int off = 16; off >= 1; off >>= 1)
#pragma unroll
            for (int c = 0; c < NC; c++)
                acc[c] += __shfl_xor_sync(0xffffffffu, acc[c], off);

        if (lane < 4) {
            float4 o = make_float4(acc[lane * 4], acc[lane * 4 + 1],
                                   acc[lane * 4 + 2], acc[lane * 4 + 3]);
            ((float4*)d_hf2)[n * 4 + lane] = o;
        }
        if (lane == 0) {
            float es = 0.f, ed = 0.f;
#pragma unroll
            for (int c = 0; c < NC; c++) {
                es = fmaf(acc[c], __ldg(&g2as[c]), es);
                ed = fmaf(acc[c], __ldg(&g2ad[c]), ed);
            }
            d_es2[n] = es;
            d_ed2[n] = ed;
        }
    }
}

// ---------------- GAT2 aggregate: 16 threads per node CSR gather ----------------
__global__ void gat2_gather(float* __restrict__ out) {
    int gid = blockIdx.x * blockDim.x + threadIdx.x;
    int n = gid >> 4;
    int l = gid & 15;
    if (n >= NN) return;

    float ed_n = d_ed2[n];
    float w = __expf(lrelu(d_es2[n] + ed_n));
    float acc = w * d_hf2[n * NC + l];
    float wsum = w;

    int r0 = d_rowptr[n];
    int r1 = d_rowptr[n + 1];
    for (int r = r0; r < r1; r++) {
        int s = __ldg(&d_cidx[r]);
        float ww = __expf(lrelu(__ldg(&d_es2[s]) + ed_n));
        acc = fmaf(ww, __ldg(&d_hf2[s * NC + l]), acc);
        wsum += ww;
    }
    out[n * NC + l] = acc / wsum;
}

// ---------------- bias + log_softmax (16 threads per node) ----------------
__global__ void finish_logsoftmax(float* __restrict__ out, const float* __restrict__ g2b) {
    int gid = blockIdx.x * blockDim.x + threadIdx.x;
    int n = gid >> 4;
    int l = gid & 15;
    if (n >= NN) return;
    float v = out[n * NC + l] + __ldg(&g2b[l]);
    float m = v;
#pragma unroll
    for (int off = 8; off >= 1; off >>= 1)
        m = fmaxf(m, __shfl_xor_sync(0xffffffffu, m, off));
    float e = __expf(v - m);
    float ssum = e;
#pragma unroll
    for (int off = 8; off >= 1; off >>= 1)
        ssum += __shfl_xor_sync(0xffffffffu, ssum, off);
    out[n * NC + l] = v - m - __logf(ssum);
}

extern "C" void kernel_launch(void* const* d_in, const int* in_sizes, int n_in,
                              void* d_out, int out_size) {
    const float* x    = (const float*)d_in[0];
    const int*   ei   = (const int*)d_in[1];     // int32 (JAX x64 disabled)
    const float* ea   = (const float*)d_in[2];
    const float* w1   = (const float*)d_in[3];
    const float* b1   = (const float*)d_in[4];
    const float* w2   = (const float*)d_in[5];
    const float* b2   = (const float*)d_in[6];
    const float* root = (const float*)d_in[7];
    const float* nnb  = (const float*)d_in[8];
    const float* g1W  = (const float*)d_in[9];
    const float* g1as = (const float*)d_in[10];
    const float* g1ad = (const float*)d_in[11];
    const float* g1b  = (const float*)d_in[12];
    const float* g2W  = (const float*)d_in[13];
    const float* g2as = (const float*)d_in[14];
    const float* g2ad = (const float*)d_in[15];
    const float* g2b  = (const float*)d_in[16];
    float* out = (float*)d_out;

    const int TB = 256;
    zero_all<<<(NN * HID + TB - 1) / TB, TB>>>();
    nnconv_edge<<<(EE + TB - 1) / TB, TB>>>(x, ei, ea, w1, b1, w2, b2);
    scan_deg<<<1, 1024>>>();
    csr_scatter<<<(EE + TB - 1) / TB, TB>>>(ei);
    nnconv_node<<<(NN + TB - 1) / TB, TB>>>(x, root, nnb);
    gat1_feat<<<(NN * 32 + TB - 1) / TB, TB>>>(g1W, g1as, g1ad);
    gat1_gather<<<(NN * 32 + TB - 1) / TB, TB>>>();
    gat2_feat<<<1024, TB>>>(g1b, g2W, g2as, g2ad);
    gat2_gather<<<(NN * 16 + TB - 1) / TB, TB>>>(out);
    finish_logsoftmax<<<(NN * 16 + TB - 1) / TB, TB>>>(out, g2b);
}

// round 4
// speedup vs baseline: 1.1802x; 1.1802x over previous
#include <cuda_runtime.h>
#include <cuda_bf16.h>
#include <math.h>

// Problem constants
#define NN 100000      // nodes
#define EE 800000      // directed edges
#define E2 (EE + NN)   // edges + self loops
#define EF 16
#define HID 8
#define H1 8
#define C1 16
#define F1 (H1 * C1)   // 128
#define NC 16

// ---------------- scratch (device globals; no allocation allowed) -------------
__device__ __align__(16) float d_h0[NN * HID];        // NNConv accum -> h0
__device__ __align__(16) float d_cnt[NN];             // in-degree
__device__ __align__(16) float d_hf1[NN * F1];        // GAT1 transformed features
__device__ __align__(16) float d_es1[NN * H1];
__device__ __align__(16) float d_ed1[NN * H1];
__device__ __align__(16) float d_z1[NN * H1];         // GAT1 softmax denom (unnorm)
__device__ __align__(16) float d_o1[NN * F1];         // GAT1 unnormalized numerator
__device__ __align__(16) float d_hf2[NN * NC];        // GAT2 transformed features
__device__ __align__(16) float d_es2[NN];
__device__ __align__(16) float d_ed2[NN];
__device__ __align__(16) float d_z2[NN];              // GAT2 softmax denom

__device__ __forceinline__ float lrelu(float v) { return v > 0.f ? v : 0.2f * v; }

// ---------------- zero accumulators ----------------
__global__ void zero_all(float* __restrict__ out) {
    int i = blockIdx.x * blockDim.x + threadIdx.x;
    if (i < NN * F1) d_o1[i] = 0.f;
    if (i < NN * HID) { d_h0[i] = 0.f; d_z1[i] = 0.f; }
    if (i < NN * NC) out[i] = 0.f;
    if (i < NN) { d_cnt[i] = 0.f; d_z2[i] = 0.f; }
}

// ---------------- NNConv edge pass: edge MLP + scatter ----------------
__global__ void nnconv_edge(const float* __restrict__ x,
                            const int* __restrict__ ei,
                            const float* __restrict__ ea,
                            const float* __restrict__ w1, const float* __restrict__ b1,
                            const float* __restrict__ w2, const float* __restrict__ b2) {
    __shared__ float sw1[EF * HID];
    __shared__ float sw2[HID * HID];
    __shared__ float sb1[HID];
    __shared__ float sb2[HID];
    int t = threadIdx.x;
    if (t < EF * HID) sw1[t] = w1[t];
    if (t < HID * HID) sw2[t] = w2[t];
    if (t < HID) { sb1[t] = b1[t]; sb2[t] = b2[t]; }
    __syncthreads();

    int e = blockIdx.x * blockDim.x + t;
    if (e >= EE) return;
    int s = ei[e];
    int d = ei[EE + e];

    float a[EF];
    const float4* ea4 = (const float4*)(ea) + e * 4;
#pragma unroll
    for (int j = 0; j < 4; j++) {
        float4 v = ea4[j];
        a[j * 4 + 0] = v.x; a[j * 4 + 1] = v.y; a[j * 4 + 2] = v.z; a[j * 4 + 3] = v.w;
    }

    float hm[HID];
#pragma unroll
    for (int k = 0; k < HID; k++) {
        float acc = sb1[k];
#pragma unroll
        for (int i = 0; i < EF; i++) acc = fmaf(a[i], sw1[i * HID + k], acc);
        hm[k] = fmaxf(acc, 0.f);
    }

    float xs = __ldg(&x[s]);
    float we[HID];
#pragma unroll
    for (int o = 0; o < HID; o++) {
        float acc = sb2[o];
#pragma unroll
        for (int k = 0; k < HID; k++) acc = fmaf(hm[k], sw2[k * HID + o], acc);
        we[o] = xs * acc;
    }
    float4* dst4 = (float4*)(&d_h0[d * HID]);
    atomicAdd(dst4 + 0, make_float4(we[0], we[1], we[2], we[3]));
    atomicAdd(dst4 + 1, make_float4(we[4], we[5], we[6], we[7]));
    atomicAdd(&d_cnt[d], 1.0f);
}

// ---------------- NNConv node pass: mean + root + relu ----------------
__global__ void nnconv_node(const float* __restrict__ x,
                            const float* __restrict__ root,
                            const float* __restrict__ nnb) {
    int n = blockIdx.x * blockDim.x + threadIdx.x;
    if (n >= NN) return;
    float inv = 1.f / fmaxf(d_cnt[n], 1.f);
    float xr = x[n];
#pragma unroll
    for (int o = 0; o < HID; o++) {
        float v = d_h0[n * HID + o] * inv + xr * __ldg(&root[o]) + __ldg(&nnb[o]);
        d_h0[n * HID + o] = fmaxf(v, 0.f);
    }
}

// ---------------- GAT1 transform: warp per node, coalesced ----------------
__global__ void gat1_feat(const float* __restrict__ g1W,
                          const float* __restrict__ g1as,
                          const float* __restrict__ g1ad) {
    int gid = blockIdx.x * blockDim.x + threadIdx.x;
    int n = gid >> 5;
    int lane = gid & 31;
    if (n >= NN) return;

    float hv = d_h0[n * HID + (lane & 7)];
    float h[HID];
#pragma unroll
    for (int k = 0; k < HID; k++) h[k] = __shfl_sync(0xffffffffu, hv, k);

    const float4* W4 = (const float4*)g1W;  // [8][32] float4
    float4 acc = make_float4(0.f, 0.f, 0.f, 0.f);
#pragma unroll
    for (int k = 0; k < HID; k++) {
        float4 w = __ldg(&W4[k * 32 + lane]);
        acc.x = fmaf(h[k], w.x, acc.x);
        acc.y = fmaf(h[k], w.y, acc.y);
        acc.z = fmaf(h[k], w.z, acc.z);
        acc.w = fmaf(h[k], w.w, acc.w);
    }
    ((float4*)d_hf1)[n * 32 + lane] = acc;

    float4 as4 = __ldg(&((const float4*)g1as)[lane]);
    float4 ad4 = __ldg(&((const float4*)g1ad)[lane]);
    float es = acc.x * as4.x + acc.y * as4.y + acc.z * as4.z + acc.w * as4.w;
    float ed = acc.x * ad4.x + acc.y * ad4.y + acc.z * ad4.z + acc.w * ad4.w;
    es += __shfl_xor_sync(0xffffffffu, es, 1);
    es += __shfl_xor_sync(0xffffffffu, es, 2);
    ed += __shfl_xor_sync(0xffffffffu, ed, 1);
    ed += __shfl_xor_sync(0xffffffffu, ed, 2);
    if ((lane & 3) == 0) {
        d_es1[n * H1 + (lane >> 2)] = es;
        d_ed1[n * H1 + (lane >> 2)] = ed;
    }
}

// ---------------- GAT1 aggregate: warp per edge, unnormalized + wsum ----------------
__global__ void gat1_aggr(const int* __restrict__ ei) {
    long long gtid = (long long)blockIdx.x * blockDim.x + threadIdx.x;
    int e = (int)(gtid >> 5);
    int lane = threadIdx.x & 31;
    if (e >= E2) return;
    int s, d;
    if (e < EE) { s = ei[e]; d = ei[EE + e]; }
    else { s = e - EE; d = s; }
    int hh = lane >> 2;   // 4 lanes (16 floats) per head
    float es = __ldg(&d_es1[s * H1 + hh]);
    float ed = __ldg(&d_ed1[d * H1 + hh]);
    float w = __expf(lrelu(es + ed));
    float4 v = __ldg(&((const float4*)d_hf1)[s * 32 + lane]);
    atomicAdd(((float4*)d_o1) + d * 32 + lane,
              make_float4(w * v.x, w * v.y, w * v.z, w * v.w));
    if ((lane & 3) == 0) atomicAdd(&d_z1[d * H1 + hh], w);
}

// ---------------- normalize + bias + ELU + GAT2 transform: warp per node ----------------
__global__ void gat2_feat(const float* __restrict__ g1b,
                          const float* __restrict__ g2W,
                          const float* __restrict__ g2as,
                          const float* __restrict__ g2ad) {
    int gid = blockIdx.x * blockDim.x + threadIdx.x;
    int lane = gid & 31;
    int warp = gid >> 5;
    int nw = (gridDim.x * blockDim.x) >> 5;

    // lane owns input rows j = 4*lane .. 4*lane+3 of W2 [128][16]
    float w[4][NC];
#pragma unroll
    for (int q = 0; q < 4; q++)
#pragma unroll
        for (int c = 0; c < NC; c++)
            w[q][c] = __ldg(&g2W[(lane * 4 + q) * NC + c]);
    float4 b4 = __ldg(&((const float4*)g1b)[lane]);

    for (int n = warp; n < NN; n += nw) {
        float zinv = 1.f / (d_z1[n * H1 + (lane >> 2)] + 1e-16f);
        float4 v4 = __ldg(&((const float4*)d_o1)[n * 32 + lane]);
        float v[4];
        v[0] = v4.x * zinv + b4.x; v[1] = v4.y * zinv + b4.y;
        v[2] = v4.z * zinv + b4.z; v[3] = v4.w * zinv + b4.w;
#pragma unroll
        for (int q = 0; q < 4; q++) v[q] = v[q] > 0.f ? v[q] : (__expf(v[q]) - 1.f);

        float acc[NC];
#pragma unroll
        for (int c = 0; c < NC; c++)
            acc[c] = v[0] * w[0][c] + v[1] * w[1][c] + v[2] * w[2][c] + v[3] * w[3][c];
#pragma unroll
        for (int off = 16; off >= 1; off >>= 1)
#pragma unroll
            for (int c = 0; c < NC; c++)
                acc[c] += __shfl_xor_sync(0xffffffffu, acc[c], off);

        if (lane < 4) {
            ((float4*)d_hf2)[n * 4 + lane] = make_float4(acc[lane * 4], acc[lane * 4 + 1],
                                                         acc[lane * 4 + 2], acc[lane * 4 + 3]);
        }
        if (lane == 0) {
            float es = 0.f, ed = 0.f;
#pragma unroll
            for (int c = 0; c < NC; c++) {
                es = fmaf(acc[c], __ldg(&g2as[c]), es);
                ed = fmaf(acc[c], __ldg(&g2ad[c]), ed);
            }
            d_es2[n] = es;
            d_ed2[n] = ed;
        }
    }
}

// ---------------- GAT2 aggregate: thread per edge, unnormalized + wsum ----------------
__global__ void gat2_aggr(const int* __restrict__ ei, float* __restrict__ out) {
    int e = blockIdx.x * blockDim.x + threadIdx.x;
    if (e >= E2) return;
    int s, d;
    if (e < EE) { s = ei[e]; d = ei[EE + e]; }
    else { s = e - EE; d = s; }
    float w = __expf(lrelu(__ldg(&d_es2[s]) + __ldg(&d_ed2[d])));
    const float4* src4 = (const float4*)(&d_hf2[s * NC]);
    float4* out4 = (float4*)(&out[d * NC]);
#pragma unroll
    for (int j = 0; j < 4; j++) {
        float4 v = __ldg(src4 + j);
        atomicAdd(out4 + j, make_float4(w * v.x, w * v.y, w * v.z, w * v.w));
    }
    atomicAdd(&d_z2[d], w);
}

// ---------------- normalize + bias + log_softmax (16 threads per node) ----------------
__global__ void finish_logsoftmax(float* __restrict__ out, const float* __restrict__ g2b) {
    int gid = blockIdx.x * blockDim.x + threadIdx.x;
    int n = gid >> 4;
    int l = gid & 15;
    if (n >= NN) return;
    float zinv = 1.f / (d_z2[n] + 1e-16f);
    float v = out[n * NC + l] * zinv + __ldg(&g2b[l]);
    float m = v;
#pragma unroll
    for (int off = 8; off >= 1; off >>= 1)
        m = fmaxf(m, __shfl_xor_sync(0xffffffffu, m, off));
    float e = __expf(v - m);
    float ssum = e;
#pragma unroll
    for (int off = 8; off >= 1; off >>= 1)
        ssum += __shfl_xor_sync(0xffffffffu, ssum, off);
    out[n * NC + l] = v - m - __logf(ssum);
}

extern "C" void kernel_launch(void* const* d_in, const int* in_sizes, int n_in,
                              void* d_out, int out_size) {
    const float* x    = (const float*)d_in[0];
    const int*   ei   = (const int*)d_in[1];     // int32 (JAX x64 disabled)
    const float* ea   = (const float*)d_in[2];
    const float* w1   = (const float*)d_in[3];
    const float* b1   = (const float*)d_in[4];
    const float* w2   = (const float*)d_in[5];
    const float* b2   = (const float*)d_in[6];
    const float* root = (const float*)d_in[7];
    const float* nnb  = (const float*)d_in[8];
    const float* g1W  = (const float*)d_in[9];
    const float* g1as = (const float*)d_in[10];
    const float* g1ad = (const float*)d_in[11];
    const float* g1b  = (const float*)d_in[12];
    const float* g2W  = (const float*)d_in[13];
    const float* g2as = (const float*)d_in[14];
    const float* g2ad = (const float*)d_in[15];
    const float* g2b  = (const float*)d_in[16];
    float* out = (float*)d_out;

    const int TB = 256;
    zero_all<<<(NN * F1 + TB - 1) / TB, TB>>>(out);
    nnconv_edge<<<(EE + TB - 1) / TB, TB>>>(x, ei, ea, w1, b1, w2, b2);
    nnconv_node<<<(NN + TB - 1) / TB, TB>>>(x, root, nnb);
    gat1_feat<<<(NN * 32 + TB - 1) / TB, TB>>>(g1W, g1as, g1ad);
    gat1_aggr<<<(int)(((long long)E2 * 32 + TB - 1) / TB), TB>>>(ei);
    gat2_feat<<<1024, TB>>>(g1b, g2W, g2as, g2ad);
    gat2_aggr<<<(E2 + TB - 1) / TB, TB>>>(ei, out);
    finish_logsoftmax<<<(NN * 16 + TB - 1) / TB, TB>>>(out, g2b);
}

// round 5
// speedup vs baseline: 1.2051x; 1.0211x over previous
#include <cuda_runtime.h>
#include <cuda_fp16.h>
#include <math.h>

// Problem constants
#define NN 100000      // nodes
#define EE 800000      // directed edges
#define EF 16
#define HID 8
#define H1 8
#define C1 16
#define F1 (H1 * C1)   // 128
#define NC 16

// ---------------- scratch (device globals; no allocation allowed) -------------
__device__ __align__(16) float d_h0[NN * HID];        // NNConv accum
__device__ __align__(16) float d_cnt[NN];             // in-degree
__device__ __align__(16) uint2 d_hf1h[NN * 32];       // GAT1 features, fp16 (4 halves/uint2)
__device__ __align__(16) float d_es1[NN * H1];
__device__ __align__(16) float d_ed1[NN * H1];
__device__ __align__(16) float d_z1[NN * H1];         // GAT1 denom (init = self-loop)
__device__ __align__(16) float d_o1[NN * F1];         // GAT1 numerator (init = self-loop)
__device__ __align__(16) float d_hf2[NN * NC];        // GAT2 transformed features
__device__ __align__(16) float d_es2[NN];
__device__ __align__(16) float d_ed2[NN];
__device__ __align__(16) float d_z2[NN];              // GAT2 denom (init = self-loop)

__device__ __forceinline__ float lrelu(float v) { return v > 0.f ? v : 0.2f * v; }

// ---------------- zero NNConv accumulators only ----------------
__global__ void zero_small() {
    int i = blockIdx.x * blockDim.x + threadIdx.x;
    if (i < NN * HID) d_h0[i] = 0.f;
    if (i < NN) d_cnt[i] = 0.f;
}

// ---------------- NNConv edge pass: edge MLP + scatter ----------------
__global__ void nnconv_edge(const float* __restrict__ x,
                            const int* __restrict__ ei,
                            const float* __restrict__ ea,
                            const float* __restrict__ w1, const float* __restrict__ b1,
                            const float* __restrict__ w2, const float* __restrict__ b2) {
    __shared__ float sw1[EF * HID];
    __shared__ float sw2[HID * HID];
    __shared__ float sb1[HID];
    __shared__ float sb2[HID];
    int t = threadIdx.x;
    if (t < EF * HID) sw1[t] = w1[t];
    if (t < HID * HID) sw2[t] = w2[t];
    if (t < HID) { sb1[t] = b1[t]; sb2[t] = b2[t]; }
    __syncthreads();

    int e = blockIdx.x * blockDim.x + t;
    if (e >= EE) return;
    int s = ei[e];
    int d = ei[EE + e];

    float a[EF];
    const float4* ea4 = (const float4*)(ea) + e * 4;
#pragma unroll
    for (int j = 0; j < 4; j++) {
        float4 v = ea4[j];
        a[j * 4 + 0] = v.x; a[j * 4 + 1] = v.y; a[j * 4 + 2] = v.z; a[j * 4 + 3] = v.w;
    }

    float hm[HID];
#pragma unroll
    for (int k = 0; k < HID; k++) {
        float acc = sb1[k];
#pragma unroll
        for (int i = 0; i < EF; i++) acc = fmaf(a[i], sw1[i * HID + k], acc);
        hm[k] = fmaxf(acc, 0.f);
    }

    float xs = __ldg(&x[s]);
    float we[HID];
#pragma unroll
    for (int o = 0; o < HID; o++) {
        float acc = sb2[o];
#pragma unroll
        for (int k = 0; k < HID; k++) acc = fmaf(hm[k], sw2[k * HID + o], acc);
        we[o] = xs * acc;
    }
    float4* dst4 = (float4*)(&d_h0[d * HID]);
    atomicAdd(dst4 + 0, make_float4(we[0], we[1], we[2], we[3]));
    atomicAdd(dst4 + 1, make_float4(we[4], we[5], we[6], we[7]));
    atomicAdd(&d_cnt[d], 1.0f);
}

// ---- fused: NNConv node epilogue + GAT1 transform + self-loop init (warp/node) ----
__global__ void gat1_feat(const float* __restrict__ x,
                          const float* __restrict__ root,
                          const float* __restrict__ nnb,
                          const float* __restrict__ g1W,
                          const float* __restrict__ g1as,
                          const float* __restrict__ g1ad) {
    int gid = blockIdx.x * blockDim.x + threadIdx.x;
    int n = gid >> 5;
    int lane = gid & 31;
    if (n >= NN) return;
    int k8 = lane & 7;

    // NNConv node epilogue: mean + root + bias + relu
    float inv = 1.f / fmaxf(d_cnt[n], 1.f);
    float xr = __ldg(&x[n]);
    float hv = d_h0[n * HID + k8] * inv + xr * __ldg(&root[k8]) + __ldg(&nnb[k8]);
    hv = fmaxf(hv, 0.f);
    float h[HID];
#pragma unroll
    for (int k = 0; k < HID; k++) h[k] = __shfl_sync(0xffffffffu, hv, k);

    // transform: lane owns 4 consecutive output cols
    const float4* W4 = (const float4*)g1W;  // [8][32] float4
    float4 acc = make_float4(0.f, 0.f, 0.f, 0.f);
#pragma unroll
    for (int k = 0; k < HID; k++) {
        float4 w = __ldg(&W4[k * 32 + lane]);
        acc.x = fmaf(h[k], w.x, acc.x);
        acc.y = fmaf(h[k], w.y, acc.y);
        acc.z = fmaf(h[k], w.z, acc.z);
        acc.w = fmaf(h[k], w.w, acc.w);
    }
    // fp16 copy for the gather pass
    __half2 lo = __floats2half2_rn(acc.x, acc.y);
    __half2 hi = __floats2half2_rn(acc.z, acc.w);
    uint2 p;
    p.x = *(const unsigned int*)&lo;
    p.y = *(const unsigned int*)&hi;
    d_hf1h[n * 32 + lane] = p;

    // attention logits per head (4 lanes per head)
    float4 as4 = __ldg(&((const float4*)g1as)[lane]);
    float4 ad4 = __ldg(&((const float4*)g1ad)[lane]);
    float es = acc.x * as4.x + acc.y * as4.y + acc.z * as4.z + acc.w * as4.w;
    float ed = acc.x * ad4.x + acc.y * ad4.y + acc.z * ad4.z + acc.w * ad4.w;
    es += __shfl_xor_sync(0xffffffffu, es, 1);
    es += __shfl_xor_sync(0xffffffffu, es, 2);
    ed += __shfl_xor_sync(0xffffffffu, ed, 1);
    ed += __shfl_xor_sync(0xffffffffu, ed, 2);

    // self-loop initialization of numerator / denominator
    float wself = __expf(lrelu(es + ed));
    ((float4*)d_o1)[n * 32 + lane] =
        make_float4(wself * acc.x, wself * acc.y, wself * acc.z, wself * acc.w);
    if ((lane & 3) == 0) {
        int hh = lane >> 2;
        d_es1[n * H1 + hh] = es;
        d_ed1[n * H1 + hh] = ed;
        d_z1[n * H1 + hh] = wself;
    }
}

// ---------------- GAT1 aggregate: warp per edge (real edges only) ----------------
__global__ void gat1_aggr(const int* __restrict__ ei) {
    long long gtid = (long long)blockIdx.x * blockDim.x + threadIdx.x;
    int e = (int)(gtid >> 5);
    int lane = threadIdx.x & 31;
    if (e >= EE) return;
    int s = ei[e];
    int d = ei[EE + e];
    int hh = lane >> 2;
    float es = __ldg(&d_es1[s * H1 + hh]);
    float ed = __ldg(&d_ed1[d * H1 + hh]);
    float w = __expf(lrelu(es + ed));
    uint2 p = __ldg(&d_hf1h[s * 32 + lane]);
    __half2 lo = *(const __half2*)&p.x;
    __half2 hi = *(const __half2*)&p.y;
    float2 flo = __half22float2(lo);
    float2 fhi = __half22float2(hi);
    atomicAdd(((float4*)d_o1) + d * 32 + lane,
              make_float4(w * flo.x, w * flo.y, w * fhi.x, w * fhi.y));
    if ((lane & 3) == 0) atomicAdd(&d_z1[d * H1 + hh], w);
}

// ---- fused: normalize + bias + ELU + GAT2 transform + self-loop init (warp/node) ----
__global__ void gat2_feat(const float* __restrict__ g1b,
                          const float* __restrict__ g2W,
                          const float* __restrict__ g2as,
                          const float* __restrict__ g2ad,
                          float* __restrict__ out) {
    int gid = blockIdx.x * blockDim.x + threadIdx.x;
    int lane = gid & 31;
    int warp = gid >> 5;
    int nw = (gridDim.x * blockDim.x) >> 5;

    float w[4][NC];
#pragma unroll
    for (int q = 0; q < 4; q++)
#pragma unroll
        for (int c = 0; c < NC; c++)
            w[q][c] = __ldg(&g2W[(lane * 4 + q) * NC + c]);
    float4 b4 = __ldg(&((const float4*)g1b)[lane]);
    float sas[NC], sad[NC];
#pragma unroll
    for (int c = 0; c < NC; c++) { sas[c] = __ldg(&g2as[c]); sad[c] = __ldg(&g2ad[c]); }

    for (int n = warp; n < NN; n += nw) {
        float zinv = 1.f / (d_z1[n * H1 + (lane >> 2)] + 1e-16f);
        float4 v4 = __ldg(&((const float4*)d_o1)[n * 32 + lane]);
        float v[4];
        v[0] = v4.x * zinv + b4.x; v[1] = v4.y * zinv + b4.y;
        v[2] = v4.z * zinv + b4.z; v[3] = v4.w * zinv + b4.w;
#pragma unroll
        for (int q = 0; q < 4; q++) v[q] = v[q] > 0.f ? v[q] : (__expf(v[q]) - 1.f);

        float acc[NC];
#pragma unroll
        for (int c = 0; c < NC; c++)
            acc[c] = v[0] * w[0][c] + v[1] * w[1][c] + v[2] * w[2][c] + v[3] * w[3][c];
#pragma unroll
        for (int off = 16; off >= 1; off >>= 1)
#pragma unroll
            for (int c = 0; c < NC; c++)
                acc[c] += __shfl_xor_sync(0xffffffffu, acc[c], off);

        float es = 0.f, ed = 0.f;
#pragma unroll
        for (int c = 0; c < NC; c++) {
            es = fmaf(acc[c], sas[c], es);
            ed = fmaf(acc[c], sad[c], ed);
        }
        float wself = __expf(lrelu(es + ed));

        if (lane < 4) {
            ((float4*)d_hf2)[n * 4 + lane] = make_float4(acc[lane * 4], acc[lane * 4 + 1],
                                                         acc[lane * 4 + 2], acc[lane * 4 + 3]);
            ((float4*)out)[n * 4 + lane] =
                make_float4(wself * acc[lane * 4], wself * acc[lane * 4 + 1],
                            wself * acc[lane * 4 + 2], wself * acc[lane * 4 + 3]);
        }
        if (lane == 0) {
            d_es2[n] = es;
            d_ed2[n] = ed;
            d_z2[n] = wself;
        }
    }
}

// ---------------- GAT2 aggregate: thread per edge (real edges only) ----------------
__global__ void gat2_aggr(const int* __restrict__ ei, float* __restrict__ out) {
    int e = blockIdx.x * blockDim.x + threadIdx.x;
    if (e >= EE) return;
    int s = ei[e];
    int d = ei[EE + e];
    float w = __expf(lrelu(__ldg(&d_es2[s]) + __ldg(&d_ed2[d])));
    const float4* src4 = (const float4*)(&d_hf2[s * NC]);
    float4* out4 = (float4*)(&out[d * NC]);
#pragma unroll
    for (int j = 0; j < 4; j++) {
        float4 v = __ldg(src4 + j);
        atomicAdd(out4 + j, make_float4(w * v.x, w * v.y, w * v.z, w * v.w));
    }
    atomicAdd(&d_z2[d], w);
}

// ---------------- normalize + bias + log_softmax (16 threads per node) ----------------
__global__ void finish_logsoftmax(float* __restrict__ out, const float* __restrict__ g2b) {
    int gid = blockIdx.x * blockDim.x + threadIdx.x;
    int n = gid >> 4;
    int l = gid & 15;
    if (n >= NN) return;
    float zinv = 1.f / (d_z2[n] + 1e-16f);
    float v = out[n * NC + l] * zinv + __ldg(&g2b[l]);
    float m = v;
#pragma unroll
    for (int off = 8; off >= 1; off >>= 1)
        m = fmaxf(m, __shfl_xor_sync(0xffffffffu, m, off));
    float e = __expf(v - m);
    float ssum = e;
#pragma unroll
    for (int off = 8; off >= 1; off >>= 1)
        ssum += __shfl_xor_sync(0xffffffffu, ssum, off);
    out[n * NC + l] = v - m - __logf(ssum);
}

extern "C" void kernel_launch(void* const* d_in, const int* in_sizes, int n_in,
                              void* d_out, int out_size) {
    const float* x    = (const float*)d_in[0];
    const int*   ei   = (const int*)d_in[1];     // int32 (JAX x64 disabled)
    const float* ea   = (const float*)d_in[2];
    const float* w1   = (const float*)d_in[3];
    const float* b1   = (const float*)d_in[4];
    const float* w2   = (const float*)d_in[5];
    const float* b2   = (const float*)d_in[6];
    const float* root = (const float*)d_in[7];
    const float* nnb  = (const float*)d_in[8];
    const float* g1W  = (const float*)d_in[9];
    const float* g1as = (const float*)d_in[10];
    const float* g1ad = (const float*)d_in[11];
    const float* g1b  = (const float*)d_in[12];
    const float* g2W  = (const float*)d_in[13];
    const float* g2as = (const float*)d_in[14];
    const float* g2ad = (const float*)d_in[15];
    const float* g2b  = (const float*)d_in[16];
    float* out = (float*)d_out;

    const int TB = 256;
    zero_small<<<(NN * HID + TB - 1) / TB, TB>>>();
    nnconv_edge<<<(EE + TB - 1) / TB, TB>>>(x, ei, ea, w1, b1, w2, b2);
    gat1_feat<<<(NN * 32 + TB - 1) / TB, TB>>>(x, root, nnb, g1W, g1as, g1ad);
    gat1_aggr<<<(int)(((long long)EE * 32 + TB - 1) / TB), TB>>>(ei);   // launch #4 -> profiled
    gat2_feat<<<1024, TB>>>(g1b, g2W, g2as, g2ad, out);
    gat2_aggr<<<(EE + TB - 1) / TB, TB>>>(ei, out);
    finish_logsoftmax<<<(NN * 16 + TB - 1) / TB, TB>>>(out, g2b);
}

// round 8
// speedup vs baseline: 1.3646x; 1.1323x over previous
#include <cuda_runtime.h>
#include <cuda_fp16.h>
#include <math.h>

// Problem constants
#define NN 100000      // nodes
#define EE 800000      // directed edges
#define EF 16
#define HID 8
#define H1 8
#define C1 16
#define F1 (H1 * C1)   // 128
#define NC 16

// ---------------- scratch (device globals; no allocation allowed) -------------
__device__ __align__(16) float d_h0[NN * HID];        // NNConv accum
__device__ __align__(16) float d_cnt[NN];             // in-degree
__device__ __align__(32) __half d_hf1h[NN * F1];      // GAT1 features, fp16
__device__ __align__(16) float d_es1[NN * H1];
__device__ __align__(16) float d_ed1[NN * H1];
__device__ __align__(16) float d_z1[NN * H1];         // GAT1 denom (init = self-loop)
__device__ __align__(32) __half d_o1h[NN * F1];       // GAT1 numerator, fp16 (v4 red target)
__device__ __align__(32) __half d_hf2h[NN * NC];      // GAT2 transformed features, fp16
__device__ __align__(16) float d_es2[NN];
__device__ __align__(16) float d_ed2[NN];
__device__ __align__(16) float d_z2[NN];              // GAT2 denom (init = self-loop)
__device__ __align__(32) __half d_o2h[NN * NC];       // GAT2 numerator, fp16 (v4 red target)

__device__ __forceinline__ float lrelu(float v) { return v > 0.f ? v : 0.2f * v; }

// one-instruction 16-byte fp16 reduction (sm_90+)
__device__ __forceinline__ void red_add_v4_f16x2(__half* addr,
                                                 unsigned int r0, unsigned int r1,
                                                 unsigned int r2, unsigned int r3) {
    asm volatile("red.global.add.noftz.v4.f16x2 [%0], {%1,%2,%3,%4};"
        :: "l"(addr), "r"(r0), "r"(r1), "r"(r2), "r"(r3)
        : "memory");
}

__device__ __forceinline__ unsigned int hmul2_u(unsigned int u, __half2 ww) {
    __half2 h = *(__half2*)&u;
    h = __hmul2(h, ww);
    return *(unsigned int*)&h;
}

// ---------------- zero NNConv accumulators only ----------------
__global__ void zero_small() {
    int i = blockIdx.x * blockDim.x + threadIdx.x;
    if (i < NN * HID) d_h0[i] = 0.f;
    if (i < NN) d_cnt[i] = 0.f;
}

// ---------------- NNConv edge pass: edge MLP + scatter ----------------
__global__ void nnconv_edge(const float* __restrict__ x,
                            const int* __restrict__ ei,
                            const float* __restrict__ ea,
                            const float* __restrict__ w1, const float* __restrict__ b1,
                            const float* __restrict__ w2, const float* __restrict__ b2) {
    __shared__ float sw1[EF * HID];
    __shared__ float sw2[HID * HID];
    __shared__ float sb1[HID];
    __shared__ float sb2[HID];
    int t = threadIdx.x;
    if (t < EF * HID) sw1[t] = w1[t];
    if (t < HID * HID) sw2[t] = w2[t];
    if (t < HID) { sb1[t] = b1[t]; sb2[t] = b2[t]; }
    __syncthreads();

    int e = blockIdx.x * blockDim.x + t;
    if (e >= EE) return;
    int s = ei[e];
    int d = ei[EE + e];

    float a[EF];
    const float4* ea4 = (const float4*)(ea) + e * 4;
#pragma unroll
    for (int j = 0; j < 4; j++) {
        float4 v = ea4[j];
        a[j * 4 + 0] = v.x; a[j * 4 + 1] = v.y; a[j * 4 + 2] = v.z; a[j * 4 + 3] = v.w;
    }

    float hm[HID];
#pragma unroll
    for (int k = 0; k < HID; k++) {
        float acc = sb1[k];
#pragma unroll
        for (int i = 0; i < EF; i++) acc = fmaf(a[i], sw1[i * HID + k], acc);
        hm[k] = fmaxf(acc, 0.f);
    }

    float xs = __ldg(&x[s]);
    float we[HID];
#pragma unroll
    for (int o = 0; o < HID; o++) {
        float acc = sb2[o];
#pragma unroll
        for (int k = 0; k < HID; k++) acc = fmaf(hm[k], sw2[k * HID + o], acc);
        we[o] = xs * acc;
    }
    float4* dst4 = (float4*)(&d_h0[d * HID]);
    atomicAdd(dst4 + 0, make_float4(we[0], we[1], we[2], we[3]));
    atomicAdd(dst4 + 1, make_float4(we[4], we[5], we[6], we[7]));
    atomicAdd(&d_cnt[d], 1.0f);
}

// ---- fused: NNConv node epilogue + GAT1 transform + self-loop init (warp/node) ----
__global__ void gat1_feat(const float* __restrict__ x,
                          const float* __restrict__ root,
                          const float* __restrict__ nnb,
                          const float* __restrict__ g1W,
                          const float* __restrict__ g1as,
                          const float* __restrict__ g1ad) {
    int gid = blockIdx.x * blockDim.x + threadIdx.x;
    int n = gid >> 5;
    int lane = gid & 31;
    if (n >= NN) return;
    int k8 = lane & 7;

    // NNConv node epilogue: mean + root + bias + relu
    float inv = 1.f / fmaxf(d_cnt[n], 1.f);
    float xr = __ldg(&x[n]);
    float hv = d_h0[n * HID + k8] * inv + xr * __ldg(&root[k8]) + __ldg(&nnb[k8]);
    hv = fmaxf(hv, 0.f);
    float h[HID];
#pragma unroll
    for (int k = 0; k < HID; k++) h[k] = __shfl_sync(0xffffffffu, hv, k);

    // transform: lane owns 4 consecutive output cols
    const float4* W4 = (const float4*)g1W;  // [8][32] float4
    float4 acc = make_float4(0.f, 0.f, 0.f, 0.f);
#pragma unroll
    for (int k = 0; k < HID; k++) {
        float4 w = __ldg(&W4[k * 32 + lane]);
        acc.x = fmaf(h[k], w.x, acc.x);
        acc.y = fmaf(h[k], w.y, acc.y);
        acc.z = fmaf(h[k], w.z, acc.z);
        acc.w = fmaf(h[k], w.w, acc.w);
    }
    // fp16 copy for the gather pass
    {
        __half2 lo = __floats2half2_rn(acc.x, acc.y);
        __half2 hi = __floats2half2_rn(acc.z, acc.w);
        uint2 p;
        p.x = *(const unsigned int*)&lo;
        p.y = *(const unsigned int*)&hi;
        ((uint2*)d_hf1h)[n * 32 + lane] = p;
    }

    // attention logits per head (4 lanes per head)
    float4 as4 = __ldg(&((const float4*)g1as)[lane]);
    float4 ad4 = __ldg(&((const float4*)g1ad)[lane]);
    float es = acc.x * as4.x + acc.y * as4.y + acc.z * as4.z + acc.w * as4.w;
    float ed = acc.x * ad4.x + acc.y * ad4.y + acc.z * ad4.z + acc.w * ad4.w;
    es += __shfl_xor_sync(0xffffffffu, es, 1);
    es += __shfl_xor_sync(0xffffffffu, es, 2);
    ed += __shfl_xor_sync(0xffffffffu, ed, 1);
    ed += __shfl_xor_sync(0xffffffffu, ed, 2);

    // self-loop initialization of numerator (fp16) / denominator (fp32)
    float wself = __expf(lrelu(es + ed));
    {
        __half2 lo = __floats2half2_rn(wself * acc.x, wself * acc.y);
        __half2 hi = __floats2half2_rn(wself * acc.z, wself * acc.w);
        uint2 p;
        p.x = *(const unsigned int*)&lo;
        p.y = *(const unsigned int*)&hi;
        ((uint2*)d_o1h)[n * 32 + lane] = p;
    }
    if ((lane & 3) == 0) {
        int hh = lane >> 2;
        d_es1[n * H1 + hh] = es;
        d_ed1[n * H1 + hh] = ed;
        d_z1[n * H1 + hh] = wself;
    }
}

// ------- GAT1 aggregate: 8 lanes/edge (one head each), two v4 reds per lane -------
__global__ void gat1_aggr(const int* __restrict__ ei) {
    long long gtid = (long long)blockIdx.x * blockDim.x + threadIdx.x;
    int e = (int)(gtid >> 3);
    int hh = (int)(gtid & 7);
    if (e >= EE) return;
    int s = __ldg(&ei[e]);
    int d = __ldg(&ei[EE + e]);

    float es = __ldg(&d_es1[s * H1 + hh]);
    float ed = __ldg(&d_ed1[d * H1 + hh]);
    float w = __expf(lrelu(es + ed));

    const uint4* hf = (const uint4*)d_hf1h;     // 8 halves per uint4
    uint4 a = __ldg(&hf[s * 16 + hh * 2]);
    uint4 b = __ldg(&hf[s * 16 + hh * 2 + 1]);
    __half2 ww = __float2half2_rn(w);

    __half* base = &d_o1h[d * F1 + hh * 16];
    red_add_v4_f16x2(base,
                     hmul2_u(a.x, ww), hmul2_u(a.y, ww),
                     hmul2_u(a.z, ww), hmul2_u(a.w, ww));
    red_add_v4_f16x2(base + 8,
                     hmul2_u(b.x, ww), hmul2_u(b.y, ww),
                     hmul2_u(b.z, ww), hmul2_u(b.w, ww));
    atomicAdd(&d_z1[d * H1 + hh], w);
}

// ---- fused: normalize + bias + ELU + GAT2 transform + self-loop init (warp/node) ----
__global__ void gat2_feat(const float* __restrict__ g1b,
                          const float* __restrict__ g2W,
                          const float* __restrict__ g2as,
                          const float* __restrict__ g2ad) {
    int gid = blockIdx.x * blockDim.x + threadIdx.x;
    int lane = gid & 31;
    int warp = gid >> 5;
    int nw = (gridDim.x * blockDim.x) >> 5;

    float w[4][NC];
#pragma unroll
    for (int q = 0; q < 4; q++)
#pragma unroll
        for (int c = 0; c < NC; c++)
            w[q][c] = __ldg(&g2W[(lane * 4 + q) * NC + c]);
    float4 b4 = __ldg(&((const float4*)g1b)[lane]);
    float sas[NC], sad[NC];
#pragma unroll
    for (int c = 0; c < NC; c++) { sas[c] = __ldg(&g2as[c]); sad[c] = __ldg(&g2ad[c]); }

    for (int n = warp; n < NN; n += nw) {
        float zinv = 1.f / (d_z1[n * H1 + (lane >> 2)] + 1e-16f);
        uint2 p = __ldg(&((const uint2*)d_o1h)[n * 32 + lane]);
        float2 flo = __half22float2(*(const __half2*)&p.x);
        float2 fhi = __half22float2(*(const __half2*)&p.y);
        float v[4];
        v[0] = flo.x * zinv + b4.x; v[1] = flo.y * zinv + b4.y;
        v[2] = fhi.x * zinv + b4.z; v[3] = fhi.y * zinv + b4.w;
#pragma unroll
        for (int q = 0; q < 4; q++) v[q] = v[q] > 0.f ? v[q] : (__expf(v[q]) - 1.f);

        float acc[NC];
#pragma unroll
        for (int c = 0; c < NC; c++)
            acc[c] = v[0] * w[0][c] + v[1] * w[1][c] + v[2] * w[2][c] + v[3] * w[3][c];
#pragma unroll
        for (int off = 16; off >= 1; off >>= 1)
#pragma unroll
            for (int c = 0; c < NC; c++)
                acc[c] += __shfl_xor_sync(0xffffffffu, acc[c], off);

        float es = 0.f, ed = 0.f;
#pragma unroll
        for (int c = 0; c < NC; c++) {
            es = fmaf(acc[c], sas[c], es);
            ed = fmaf(acc[c], sad[c], ed);
        }
        float wself = __expf(lrelu(es + ed));

        if (lane < 2) {   // each of 2 lanes packs 8 halves (one uint4)
            unsigned int hp[4], op[4];
#pragma unroll
            for (int q = 0; q < 4; q++) {
                float va = acc[lane * 8 + 2 * q];
                float vb = acc[lane * 8 + 2 * q + 1];
                __half2 h = __floats2half2_rn(va, vb);
                hp[q] = *(const unsigned int*)&h;
                __half2 o = __floats2half2_rn(wself * va, wself * vb);
                op[q] = *(const unsigned int*)&o;
            }
            ((uint4*)d_hf2h)[n * 2 + lane] = make_uint4(hp[0], hp[1], hp[2], hp[3]);
            ((uint4*)d_o2h)[n * 2 + lane] = make_uint4(op[0], op[1], op[2], op[3]);
        }
        if (lane == 0) {
            d_es2[n] = es;
            d_ed2[n] = ed;
            d_z2[n] = wself;
        }
    }
}

// ------- GAT2 aggregate: thread per edge, two v4 reds cover the node row -------
__global__ void gat2_aggr(const int* __restrict__ ei) {
    int e = blockIdx.x * blockDim.x + threadIdx.x;
    if (e >= EE) return;
    int s = ei[e];
    int d = ei[EE + e];
    float w = __expf(lrelu(__ldg(&d_es2[s]) + __ldg(&d_ed2[d])));
    const uint4* hf = (const uint4*)d_hf2h;
    uint4 a = __ldg(&hf[s * 2]);
    uint4 b = __ldg(&hf[s * 2 + 1]);
    __half2 ww = __float2half2_rn(w);
    __half* base = &d_o2h[d * NC];
    red_add_v4_f16x2(base,
                     hmul2_u(a.x, ww), hmul2_u(a.y, ww),
                     hmul2_u(a.z, ww), hmul2_u(a.w, ww));
    red_add_v4_f16x2(base + 8,
                     hmul2_u(b.x, ww), hmul2_u(b.y, ww),
                     hmul2_u(b.z, ww), hmul2_u(b.w, ww));
    atomicAdd(&d_z2[d], w);
}

// ------- normalize + bias + log_softmax (16 threads per node), fp32 output -------
__global__ void finish_logsoftmax(float* __restrict__ out, const float* __restrict__ g2b) {
    int gid = blockIdx.x * blockDim.x + threadIdx.x;
    int n = gid >> 4;
    int l = gid & 15;
    if (n >= NN) return;
    float zinv = 1.f / (d_z2[n] + 1e-16f);
    float v = __half2float(d_o2h[n * NC + l]) * zinv + __ldg(&g2b[l]);
    float m = v;
#pragma unroll
    for (int off = 8; off >= 1; off >>= 1)
        m = fmaxf(m, __shfl_xor_sync(0xffffffffu, m, off));
    float e = __expf(v - m);
    float ssum = e;
#pragma unroll
    for (int off = 8; off >= 1; off >>= 1)
        ssum += __shfl_xor_sync(0xffffffffu, ssum, off);
    out[n * NC + l] = v - m - __logf(ssum);
}

extern "C" void kernel_launch(void* const* d_in, const int* in_sizes, int n_in,
                              void* d_out, int out_size) {
    const float* x    = (const float*)d_in[0];
    const int*   ei   = (const int*)d_in[1];     // int32 (JAX x64 disabled)
    const float* ea   = (const float*)d_in[2];
    const float* w1   = (const float*)d_in[3];
    const float* b1   = (const float*)d_in[4];
    const float* w2   = (const float*)d_in[5];
    const float* b2   = (const float*)d_in[6];
    const float* root = (const float*)d_in[7];
    const float* nnb  = (const float*)d_in[8];
    const float* g1W  = (const float*)d_in[9];
    const float* g1as = (const float*)d_in[10];
    const float* g1ad = (const float*)d_in[11];
    const float* g1b  = (const float*)d_in[12];
    const float* g2W  = (const float*)d_in[13];
    const float* g2as = (const float*)d_in[14];
    const float* g2ad = (const float*)d_in[15];
    const float* g2b  = (const float*)d_in[16];
    float* out = (float*)d_out;

    const int TB = 256;
    zero_small<<<(NN * HID + TB - 1) / TB, TB>>>();
    nnconv_edge<<<(EE + TB - 1) / TB, TB>>>(x, ei, ea, w1, b1, w2, b2);
    gat1_feat<<<(NN * 32 + TB - 1) / TB, TB>>>(x, root, nnb, g1W, g1as, g1ad);
    gat1_aggr<<<(int)(((long long)EE * 8 + TB - 1) / TB), TB>>>(ei);   // launch #4 -> profiled
    gat2_feat<<<1024, TB>>>(g1b, g2W, g2as, g2ad);
    gat2_aggr<<<(EE + TB - 1) / TB, TB>>>(ei);
    finish_logsoftmax<<<(NN * 16 + TB - 1) / TB, TB>>>(out, g2b);
}

// round 9
// speedup vs baseline: 1.4479x; 1.0611x over previous
#include <cuda_runtime.h>
#include <cuda_fp16.h>
#include <math.h>

// Problem constants
#define NN 100000      // nodes
#define EE 800000      // directed edges
#define EF 16
#define HID 8
#define H1 8
#define C1 16
#define F1 (H1 * C1)   // 128
#define NC 16

// ---------------- scratch (device globals; no allocation allowed) -------------
__device__ __align__(16) float d_h0[NN * HID];        // NNConv accum
__device__ __align__(16) float d_cnt[NN];             // in-degree
__device__ __align__(32) __half d_hf1h[NN * F1];      // GAT1 features, fp16
__device__ __align__(16) unsigned int d_e1[NN * H1];  // packed half2(es,ed) per head
__device__ __align__(16) float d_z1[NN * H1];         // GAT1 denom (init = self-loop)
__device__ __align__(32) __half d_o1h[NN * F1];       // GAT1 numerator, fp16 (v4 red target)
__device__ __align__(32) __half d_hf2h[NN * NC];      // GAT2 transformed features, fp16
__device__ __align__(16) unsigned int d_e2[NN];       // packed half2(es,ed)
__device__ __align__(16) float d_z2[NN];              // GAT2 denom (init = self-loop)
__device__ __align__(32) __half d_o2h[NN * NC];       // GAT2 numerator, fp16 (v4 red target)

__device__ __forceinline__ float lrelu(float v) { return v > 0.f ? v : 0.2f * v; }

// one-instruction 16-byte fp16 reduction (sm_90+)
__device__ __forceinline__ void red_add_v4_f16x2(__half* addr,
                                                 unsigned int r0, unsigned int r1,
                                                 unsigned int r2, unsigned int r3) {
    asm volatile("red.global.add.noftz.v4.f16x2 [%0], {%1,%2,%3,%4};"
        :: "l"(addr), "r"(r0), "r"(r1), "r"(r2), "r"(r3)
        : "memory");
}

__device__ __forceinline__ unsigned int hmul2_u(unsigned int u, __half2 ww) {
    __half2 h = *(__half2*)&u;
    h = __hmul2(h, ww);
    return *(unsigned int*)&h;
}

__device__ __forceinline__ unsigned int pack_esed(float es, float ed) {
    __half2 h = __floats2half2_rn(es, ed);
    return *(const unsigned int*)&h;
}

// ---------------- zero NNConv accumulators (3 small launches) ----------------
__global__ void zero_a() {
    int i = blockIdx.x * blockDim.x + threadIdx.x;
    if (i < NN * HID / 2) d_h0[i] = 0.f;
}
__global__ void zero_b() {
    int i = blockIdx.x * blockDim.x + threadIdx.x;
    if (i < NN * HID / 2) d_h0[NN * HID / 2 + i] = 0.f;
}
__global__ void zero_c() {
    int i = blockIdx.x * blockDim.x + threadIdx.x;
    if (i < NN) d_cnt[i] = 0.f;
}

// ---------------- NNConv edge pass: edge MLP + scatter (launch #4: profiled) ----------------
__global__ void nnconv_edge(const float* __restrict__ x,
                            const int* __restrict__ ei,
                            const float* __restrict__ ea,
                            const float* __restrict__ w1, const float* __restrict__ b1,
                            const float* __restrict__ w2, const float* __restrict__ b2) {
    __shared__ float sw1[EF * HID];
    __shared__ float sw2[HID * HID];
    __shared__ float sb1[HID];
    __shared__ float sb2[HID];
    int t = threadIdx.x;
    if (t < EF * HID) sw1[t] = w1[t];
    if (t < HID * HID) sw2[t] = w2[t];
    if (t < HID) { sb1[t] = b1[t]; sb2[t] = b2[t]; }
    __syncthreads();

    int e = blockIdx.x * blockDim.x + t;
    if (e >= EE) return;
    int s = ei[e];
    int d = ei[EE + e];

    float a[EF];
    const float4* ea4 = (const float4*)(ea) + e * 4;
#pragma unroll
    for (int j = 0; j < 4; j++) {
        float4 v = ea4[j];
        a[j * 4 + 0] = v.x; a[j * 4 + 1] = v.y; a[j * 4 + 2] = v.z; a[j * 4 + 3] = v.w;
    }

    float hm[HID];
#pragma unroll
    for (int k = 0; k < HID; k++) {
        float acc = sb1[k];
#pragma unroll
        for (int i = 0; i < EF; i++) acc = fmaf(a[i], sw1[i * HID + k], acc);
        hm[k] = fmaxf(acc, 0.f);
    }

    float xs = __ldg(&x[s]);
    float we[HID];
#pragma unroll
    for (int o = 0; o < HID; o++) {
        float acc = sb2[o];
#pragma unroll
        for (int k = 0; k < HID; k++) acc = fmaf(hm[k], sw2[k * HID + o], acc);
        we[o] = xs * acc;
    }
    float4* dst4 = (float4*)(&d_h0[d * HID]);
    atomicAdd(dst4 + 0, make_float4(we[0], we[1], we[2], we[3]));
    atomicAdd(dst4 + 1, make_float4(we[4], we[5], we[6], we[7]));
    atomicAdd(&d_cnt[d], 1.0f);
}

// ---- fused: NNConv node epilogue + GAT1 transform + self-loop init (warp/node) ----
__global__ void gat1_feat(const float* __restrict__ x,
                          const float* __restrict__ root,
                          const float* __restrict__ nnb,
                          const float* __restrict__ g1W,
                          const float* __restrict__ g1as,
                          const float* __restrict__ g1ad) {
    int gid = blockIdx.x * blockDim.x + threadIdx.x;
    int n = gid >> 5;
    int lane = gid & 31;
    if (n >= NN) return;
    int k8 = lane & 7;

    // NNConv node epilogue: mean + root + bias + relu
    float inv = 1.f / fmaxf(d_cnt[n], 1.f);
    float xr = __ldg(&x[n]);
    float hv = d_h0[n * HID + k8] * inv + xr * __ldg(&root[k8]) + __ldg(&nnb[k8]);
    hv = fmaxf(hv, 0.f);
    float h[HID];
#pragma unroll
    for (int k = 0; k < HID; k++) h[k] = __shfl_sync(0xffffffffu, hv, k);

    // transform: lane owns 4 consecutive output cols
    const float4* W4 = (const float4*)g1W;  // [8][32] float4
    float4 acc = make_float4(0.f, 0.f, 0.f, 0.f);
#pragma unroll
    for (int k = 0; k < HID; k++) {
        float4 w = __ldg(&W4[k * 32 + lane]);
        acc.x = fmaf(h[k], w.x, acc.x);
        acc.y = fmaf(h[k], w.y, acc.y);
        acc.z = fmaf(h[k], w.z, acc.z);
        acc.w = fmaf(h[k], w.w, acc.w);
    }
    // fp16 copy for the gather pass
    {
        __half2 lo = __floats2half2_rn(acc.x, acc.y);
        __half2 hi = __floats2half2_rn(acc.z, acc.w);
        uint2 p;
        p.x = *(const unsigned int*)&lo;
        p.y = *(const unsigned int*)&hi;
        ((uint2*)d_hf1h)[n * 32 + lane] = p;
    }

    // attention logits per head (4 lanes per head)
    float4 as4 = __ldg(&((const float4*)g1as)[lane]);
    float4 ad4 = __ldg(&((const float4*)g1ad)[lane]);
    float es = acc.x * as4.x + acc.y * as4.y + acc.z * as4.z + acc.w * as4.w;
    float ed = acc.x * ad4.x + acc.y * ad4.y + acc.z * ad4.z + acc.w * ad4.w;
    es += __shfl_xor_sync(0xffffffffu, es, 1);
    es += __shfl_xor_sync(0xffffffffu, es, 2);
    ed += __shfl_xor_sync(0xffffffffu, ed, 1);
    ed += __shfl_xor_sync(0xffffffffu, ed, 2);

    // self-loop initialization of numerator (fp16) / denominator (fp32)
    float wself = __expf(lrelu(es + ed));
    {
        __half2 lo = __floats2half2_rn(wself * acc.x, wself * acc.y);
        __half2 hi = __floats2half2_rn(wself * acc.z, wself * acc.w);
        uint2 p;
        p.x = *(const unsigned int*)&lo;
        p.y = *(const unsigned int*)&hi;
        ((uint2*)d_o1h)[n * 32 + lane] = p;
    }
    if ((lane & 3) == 0) {
        int hh = lane >> 2;
        d_e1[n * H1 + hh] = pack_esed(es, ed);
        d_z1[n * H1 + hh] = wself;
    }
}

// ------- GAT1 aggregate: 8 lanes/edge (one head each), two v4 reds per lane -------
__global__ void gat1_aggr(const int* __restrict__ ei) {
    long long gtid = (long long)blockIdx.x * blockDim.x + threadIdx.x;
    int e = (int)(gtid >> 3);
    int hh = (int)(gtid & 7);
    if (e >= EE) return;
    int s = __ldg(&ei[e]);
    int d = __ldg(&ei[EE + e]);

    unsigned int ps = __ldg(&d_e1[s * H1 + hh]);
    unsigned int pd = __ldg(&d_e1[d * H1 + hh]);
    float es = __low2float(*(const __half2*)&ps);
    float ed = __high2float(*(const __half2*)&pd);
    float w = __expf(lrelu(es + ed));

    const uint4* hf = (const uint4*)d_hf1h;     // 8 halves per uint4
    uint4 a = __ldg(&hf[s * 16 + hh * 2]);
    uint4 b = __ldg(&hf[s * 16 + hh * 2 + 1]);
    __half2 ww = __float2half2_rn(w);

    __half* base = &d_o1h[d * F1 + hh * 16];
    red_add_v4_f16x2(base,
                     hmul2_u(a.x, ww), hmul2_u(a.y, ww),
                     hmul2_u(a.z, ww), hmul2_u(a.w, ww));
    red_add_v4_f16x2(base + 8,
                     hmul2_u(b.x, ww), hmul2_u(b.y, ww),
                     hmul2_u(b.z, ww), hmul2_u(b.w, ww));
    atomicAdd(&d_z1[d * H1 + hh], w);
}

// ---- fused: normalize + bias + ELU + GAT2 transform + self-loop init (warp/node) ----
__global__ void gat2_feat(const float* __restrict__ g1b,
                          const float* __restrict__ g2W,
                          const float* __restrict__ g2as,
                          const float* __restrict__ g2ad) {
    int gid = blockIdx.x * blockDim.x + threadIdx.x;
    int lane = gid & 31;
    int warp = gid >> 5;
    int nw = (gridDim.x * blockDim.x) >> 5;

    float w[4][NC];
#pragma unroll
    for (int q = 0; q < 4; q++)
#pragma unroll
        for (int c = 0; c < NC; c++)
            w[q][c] = __ldg(&g2W[(lane * 4 + q) * NC + c]);
    float4 b4 = __ldg(&((const float4*)g1b)[lane]);
    float sas[NC], sad[NC];
#pragma unroll
    for (int c = 0; c < NC; c++) { sas[c] = __ldg(&g2as[c]); sad[c] = __ldg(&g2ad[c]); }

    for (int n = warp; n < NN; n += nw) {
        float zinv = 1.f / (d_z1[n * H1 + (lane >> 2)] + 1e-16f);
        uint2 p = __ldg(&((const uint2*)d_o1h)[n * 32 + lane]);
        float2 flo = __half22float2(*(const __half2*)&p.x);
        float2 fhi = __half22float2(*(const __half2*)&p.y);
        float v[4];
        v[0] = flo.x * zinv + b4.x; v[1] = flo.y * zinv + b4.y;
        v[2] = fhi.x * zinv + b4.z; v[3] = fhi.y * zinv + b4.w;
#pragma unroll
        for (int q = 0; q < 4; q++) v[q] = v[q] > 0.f ? v[q] : (__expf(v[q]) - 1.f);

        float acc[NC];
#pragma unroll
        for (int c = 0; c < NC; c++)
            acc[c] = v[0] * w[0][c] + v[1] * w[1][c] + v[2] * w[2][c] + v[3] * w[3][c];
#pragma unroll
        for (int off = 16; off >= 1; off >>= 1)
#pragma unroll
            for (int c = 0; c < NC; c++)
                acc[c] += __shfl_xor_sync(0xffffffffu, acc[c], off);

        float es = 0.f, ed = 0.f;
#pragma unroll
        for (int c = 0; c < NC; c++) {
            es = fmaf(acc[c], sas[c], es);
            ed = fmaf(acc[c], sad[c], ed);
        }
        float wself = __expf(lrelu(es + ed));

        if (lane < 2) {   // each of 2 lanes packs 8 halves (one uint4)
            unsigned int hp[4], op[4];
#pragma unroll
            for (int q = 0; q < 4; q++) {
                float va = acc[lane * 8 + 2 * q];
                float vb = acc[lane * 8 + 2 * q + 1];
                __half2 h = __floats2half2_rn(va, vb);
                hp[q] = *(const unsigned int*)&h;
                __half2 o = __floats2half2_rn(wself * va, wself * vb);
                op[q] = *(const unsigned int*)&o;
            }
            ((uint4*)d_hf2h)[n * 2 + lane] = make_uint4(hp[0], hp[1], hp[2], hp[3]);
            ((uint4*)d_o2h)[n * 2 + lane] = make_uint4(op[0], op[1], op[2], op[3]);
        }
        if (lane == 0) {
            d_e2[n] = pack_esed(es, ed);
            d_z2[n] = wself;
        }
    }
}

// ------- GAT2 aggregate: thread per edge, two v4 reds cover the node row -------
__global__ void gat2_aggr(const int* __restrict__ ei) {
    int e = blockIdx.x * blockDim.x + threadIdx.x;
    if (e >= EE) return;
    int s = ei[e];
    int d = ei[EE + e];
    unsigned int ps = __ldg(&d_e2[s]);
    unsigned int pd = __ldg(&d_e2[d]);
    float es = __low2float(*(const __half2*)&ps);
    float ed = __high2float(*(const __half2*)&pd);
    float w = __expf(lrelu(es + ed));
    const uint4* hf = (const uint4*)d_hf2h;
    uint4 a = __ldg(&hf[s * 2]);
    uint4 b = __ldg(&hf[s * 2 + 1]);
    __half2 ww = __float2half2_rn(w);
    __half* base = &d_o2h[d * NC];
    red_add_v4_f16x2(base,
                     hmul2_u(a.x, ww), hmul2_u(a.y, ww),
                     hmul2_u(a.z, ww), hmul2_u(a.w, ww));
    red_add_v4_f16x2(base + 8,
                     hmul2_u(b.x, ww), hmul2_u(b.y, ww),
                     hmul2_u(b.z, ww), hmul2_u(b.w, ww));
    atomicAdd(&d_z2[d], w);
}

// ------- normalize + bias + log_softmax (16 threads per node), fp32 output -------
__global__ void finish_logsoftmax(float* __restrict__ out, const float* __restrict__ g2b) {
    int gid = blockIdx.x * blockDim.x + threadIdx.x;
    int n = gid >> 4;
    int l = gid & 15;
    if (n >= NN) return;
    float zinv = 1.f / (d_z2[n] + 1e-16f);
    float v = __half2float(d_o2h[n * NC + l]) * zinv + __ldg(&g2b[l]);
    float m = v;
#pragma unroll
    for (int off = 8; off >= 1; off >>= 1)
        m = fmaxf(m, __shfl_xor_sync(0xffffffffu, m, off));
    float e = __expf(v - m);
    float ssum = e;
#pragma unroll
    for (int off = 8; off >= 1; off >>= 1)
        ssum += __shfl_xor_sync(0xffffffffu, ssum, off);
    out[n * NC + l] = v - m - __logf(ssum);
}

extern "C" void kernel_launch(void* const* d_in, const int* in_sizes, int n_in,
                              void* d_out, int out_size) {
    const float* x    = (const float*)d_in[0];
    const int*   ei   = (const int*)d_in[1];     // int32 (JAX x64 disabled)
    const float* ea   = (const float*)d_in[2];
    const float* w1   = (const float*)d_in[3];
    const float* b1   = (const float*)d_in[4];
    const float* w2   = (const float*)d_in[5];
    const float* b2   = (const float*)d_in[6];
    const float* root = (const float*)d_in[7];
    const float* nnb  = (const float*)d_in[8];
    const float* g1W  = (const float*)d_in[9];
    const float* g1as = (const float*)d_in[10];
    const float* g1ad = (const float*)d_in[11];
    const float* g1b  = (const float*)d_in[12];
    const float* g2W  = (const float*)d_in[13];
    const float* g2as = (const float*)d_in[14];
    const float* g2ad = (const float*)d_in[15];
    const float* g2b  = (const float*)d_in[16];
    float* out = (float*)d_out;

    const int TB = 256;
    zero_a<<<(NN * HID / 2 + TB - 1) / TB, TB>>>();
    zero_b<<<(NN * HID / 2 + TB - 1) / TB, TB>>>();
    zero_c<<<(NN + TB - 1) / TB, TB>>>();
    nnconv_edge<<<(EE + TB - 1) / TB, TB>>>(x, ei, ea, w1, b1, w2, b2);   // launch #4 -> profiled
    gat1_feat<<<(NN * 32 + TB - 1) / TB, TB>>>(x, root, nnb, g1W, g1as, g1ad);
    gat1_aggr<<<(int)(((long long)EE * 8 + TB - 1) / TB), TB>>>(ei);
    gat2_feat<<<1024, TB>>>(g1b, g2W, g2as, g2ad);
    gat2_aggr<<<(EE + TB - 1) / TB, TB>>>(ei);
    finish_logsoftmax<<<(NN * 16 + TB - 1) / TB, TB>>>(out, g2b);
}

// round 11
// speedup vs baseline: 1.7159x; 1.1851x over previous
#include <cuda_runtime.h>
#include <cuda_fp16.h>
#include <math.h>

// Problem constants
#define NN 100000      // nodes
#define EE 800000      // directed edges
#define EF 16
#define HID 8
#define H1 8
#define C1 16
#define F1 (H1 * C1)   // 128
#define NC 16

// ---------------- scratch (device globals; no allocation allowed) -------------
__device__ __align__(16) float d_h0[NN * HID];        // NNConv accum
__device__ __align__(16) float d_cnt[NN];             // in-degree
__device__ __align__(32) __half d_hf1h[NN * F1];      // GAT1 features, fp16
__device__ __align__(16) unsigned int d_e1[NN * H1];  // packed half2(es,ed) per head
__device__ __align__(16) float d_z1[NN * H1];         // GAT1 denom (init = self-loop)
__device__ __align__(32) __half d_o1h[NN * F1];       // GAT1 numerator, fp16 (v4 red target)
__device__ __align__(32) __half d_hf2h[NN * NC];      // GAT2 transformed features, fp16
__device__ __align__(16) unsigned int d_e2[NN];       // packed half2(es,ed)
__device__ __align__(16) float d_z2[NN];              // GAT2 denom (init = self-loop)
__device__ __align__(32) __half d_o2h[NN * NC];       // GAT2 numerator, fp16 (v4 red target)

__device__ __forceinline__ float lrelu(float v) { return v > 0.f ? v : 0.2f * v; }

// one-instruction 16-byte fp16 reduction (sm_90+)
__device__ __forceinline__ void red_add_v4_f16x2(__half* addr,
                                                 unsigned int r0, unsigned int r1,
                                                 unsigned int r2, unsigned int r3) {
    asm volatile("red.global.add.noftz.v4.f16x2 [%0], {%1,%2,%3,%4};"
        :: "l"(addr), "r"(r0), "r"(r1), "r"(r2), "r"(r3)
        : "memory");
}

__device__ __forceinline__ unsigned int hmul2_u(unsigned int u, __half2 ww) {
    __half2 h = *(__half2*)&u;
    h = __hmul2(h, ww);
    return *(unsigned int*)&h;
}

__device__ __forceinline__ unsigned int pack_esed(float es, float ed) {
    __half2 h = __floats2half2_rn(es, ed);
    return *(const unsigned int*)&h;
}

// ---------------- NNConv edge pass: edge MLP + scatter ----------------
__global__ void nnconv_edge(const float* __restrict__ x,
                            const int* __restrict__ ei,
                            const float* __restrict__ ea,
                            const float* __restrict__ w1, const float* __restrict__ b1,
                            const float* __restrict__ w2, const float* __restrict__ b2) {
    __shared__ float sw1[EF * HID];
    __shared__ float sw2[HID * HID];
    __shared__ float sb1[HID];
    __shared__ float sb2[HID];
    int t = threadIdx.x;
    if (t < EF * HID) sw1[t] = w1[t];
    if (t < HID * HID) sw2[t] = w2[t];
    if (t < HID) { sb1[t] = b1[t]; sb2[t] = b2[t]; }
    __syncthreads();

    int e = blockIdx.x * blockDim.x + t;
    if (e >= EE) return;
    int s = ei[e];
    int d = ei[EE + e];

    float a[EF];
    const float4* ea4 = (const float4*)(ea) + e * 4;
#pragma unroll
    for (int j = 0; j < 4; j++) {
        float4 v = ea4[j];
        a[j * 4 + 0] = v.x; a[j * 4 + 1] = v.y; a[j * 4 + 2] = v.z; a[j * 4 + 3] = v.w;
    }

    float hm[HID];
#pragma unroll
    for (int k = 0; k < HID; k++) {
        float acc = sb1[k];
#pragma unroll
        for (int i = 0; i < EF; i++) acc = fmaf(a[i], sw1[i * HID + k], acc);
        hm[k] = fmaxf(acc, 0.f);
    }

    float xs = __ldg(&x[s]);
    float we[HID];
#pragma unroll
    for (int o = 0; o < HID; o++) {
        float acc = sb2[o];
#pragma unroll
        for (int k = 0; k < HID; k++) acc = fmaf(hm[k], sw2[k * HID + o], acc);
        we[o] = xs * acc;
    }
    float4* dst4 = (float4*)(&d_h0[d * HID]);
    atomicAdd(dst4 + 0, make_float4(we[0], we[1], we[2], we[3]));
    atomicAdd(dst4 + 1, make_float4(we[4], we[5], we[6], we[7]));
    atomicAdd(&d_cnt[d], 1.0f);
}

// ---- fused: NNConv node epilogue + GAT1 transform + self-loop init (warp/node) ----
__global__ void gat1_feat(const float* __restrict__ x,
                          const float* __restrict__ root,
                          const float* __restrict__ nnb,
                          const float* __restrict__ g1W,
                          const float* __restrict__ g1as,
                          const float* __restrict__ g1ad) {
    int gid = blockIdx.x * blockDim.x + threadIdx.x;
    int n = gid >> 5;
    int lane = gid & 31;
    if (n >= NN) return;
    int k8 = lane & 7;

    float inv = 1.f / fmaxf(d_cnt[n], 1.f);
    float xr = __ldg(&x[n]);
    float hv = d_h0[n * HID + k8] * inv + xr * __ldg(&root[k8]) + __ldg(&nnb[k8]);
    hv = fmaxf(hv, 0.f);
    float h[HID];
#pragma unroll
    for (int k = 0; k < HID; k++) h[k] = __shfl_sync(0xffffffffu, hv, k);

    const float4* W4 = (const float4*)g1W;  // [8][32] float4
    float4 acc = make_float4(0.f, 0.f, 0.f, 0.f);
#pragma unroll
    for (int k = 0; k < HID; k++) {
        float4 w = __ldg(&W4[k * 32 + lane]);
        acc.x = fmaf(h[k], w.x, acc.x);
        acc.y = fmaf(h[k], w.y, acc.y);
        acc.z = fmaf(h[k], w.z, acc.z);
        acc.w = fmaf(h[k], w.w, acc.w);
    }
    {
        __half2 lo = __floats2half2_rn(acc.x, acc.y);
        __half2 hi = __floats2half2_rn(acc.z, acc.w);
        uint2 p;
        p.x = *(const unsigned int*)&lo;
        p.y = *(const unsigned int*)&hi;
        ((uint2*)d_hf1h)[n * 32 + lane] = p;
    }

    float4 as4 = __ldg(&((const float4*)g1as)[lane]);
    float4 ad4 = __ldg(&((const float4*)g1ad)[lane]);
    float es = acc.x * as4.x + acc.y * as4.y + acc.z * as4.z + acc.w * as4.w;
    float ed = acc.x * ad4.x + acc.y * ad4.y + acc.z * ad4.z + acc.w * ad4.w;
    es += __shfl_xor_sync(0xffffffffu, es, 1);
    es += __shfl_xor_sync(0xffffffffu, es, 2);
    ed += __shfl_xor_sync(0xffffffffu, ed, 1);
    ed += __shfl_xor_sync(0xffffffffu, ed, 2);

    float wself = __expf(lrelu(es + ed));
    {
        __half2 lo = __floats2half2_rn(wself * acc.x, wself * acc.y);
        __half2 hi = __floats2half2_rn(wself * acc.z, wself * acc.w);
        uint2 p;
        p.x = *(const unsigned int*)&lo;
        p.y = *(const unsigned int*)&hi;
        ((uint2*)d_o1h)[n * 32 + lane] = p;
    }
    if ((lane & 3) == 0) {
        int hh = lane >> 2;
        d_e1[n * H1 + hh] = pack_esed(es, ed);
        d_z1[n * H1 + hh] = wself;
    }
}

// ------- GAT1 aggregate: 8 lanes/edge (one head each), two v4 reds per lane -------
__global__ void gat1_aggr(const int* __restrict__ ei) {
    long long gtid = (long long)blockIdx.x * blockDim.x + threadIdx.x;
    int e = (int)(gtid >> 3);
    int hh = (int)(gtid & 7);
    if (e >= EE) return;
    int s = __ldg(&ei[e]);
    int d = __ldg(&ei[EE + e]);

    unsigned int ps = __ldg(&d_e1[s * H1 + hh]);
    unsigned int pd = __ldg(&d_e1[d * H1 + hh]);
    float es = __low2float(*(const __half2*)&ps);
    float ed = __high2float(*(const __half2*)&pd);
    float w = __expf(lrelu(es + ed));

    const uint4* hf = (const uint4*)d_hf1h;     // 8 halves per uint4
    uint4 a = __ldg(&hf[s * 16 + hh * 2]);
    uint4 b = __ldg(&hf[s * 16 + hh * 2 + 1]);
    __half2 ww = __float2half2_rn(w);

    __half* base = &d_o1h[d * F1 + hh * 16];
    red_add_v4_f16x2(base,
                     hmul2_u(a.x, ww), hmul2_u(a.y, ww),
                     hmul2_u(a.z, ww), hmul2_u(a.w, ww));
    red_add_v4_f16x2(base + 8,
                     hmul2_u(b.x, ww), hmul2_u(b.y, ww),
                     hmul2_u(b.z, ww), hmul2_u(b.w, ww));
    atomicAdd(&d_z1[d * H1 + hh], w);
}

// ---- fused: normalize + bias + ELU + GAT2 transform + self-loop init (warp/node) ----
// Reduce-scatter: 47 shfls/node; lane l ends owning output l&15.
__global__ void gat2_feat(const float* __restrict__ g1b,
                          const float* __restrict__ g2W,
                          const float* __restrict__ g2as,
                          const float* __restrict__ g2ad) {
    int gid = blockIdx.x * blockDim.x + threadIdx.x;
    int lane = gid & 31;
    int warp = gid >> 5;
    int nw = (gridDim.x * blockDim.x) >> 5;

    float w[4][NC];
#pragma unroll
    for (int q = 0; q < 4; q++)
#pragma unroll
        for (int c = 0; c < NC; c++)
            w[q][c] = __ldg(&g2W[(lane * 4 + q) * NC + c]);
    float4 b4 = __ldg(&((const float4*)g1b)[lane]);
    int oidx = lane & 15;
    float sas_own = __ldg(&g2as[oidx]);
    float sad_own = __ldg(&g2ad[oidx]);

    for (int n = warp; n < NN; n += nw) {
        float zinv = 1.f / (d_z1[n * H1 + (lane >> 2)] + 1e-16f);
        uint2 p = __ldg(&((const uint2*)d_o1h)[n * 32 + lane]);
        float2 flo = __half22float2(*(const __half2*)&p.x);
        float2 fhi = __half22float2(*(const __half2*)&p.y);
        float v[4];
        v[0] = flo.x * zinv + b4.x; v[1] = flo.y * zinv + b4.y;
        v[2] = fhi.x * zinv + b4.z; v[3] = fhi.y * zinv + b4.w;
#pragma unroll
        for (int q = 0; q < 4; q++) v[q] = v[q] > 0.f ? v[q] : (__expf(v[q]) - 1.f);

        float acc[NC];
#pragma unroll
        for (int c = 0; c < NC; c++)
            acc[c] = v[0] * w[0][c] + v[1] * w[1][c] + v[2] * w[2][c] + v[3] * w[3][c];

        // fold upper half-warp onto lower (full 16-vector)
#pragma unroll
        for (int c = 0; c < NC; c++)
            acc[c] += __shfl_xor_sync(0xffffffffu, acc[c], 16);
        // reduce-scatter
        float a8[8];
#pragma unroll
        for (int j = 0; j < 8; j++) {
            float snd = (lane & 8) ? acc[j] : acc[j + 8];
            float r = __shfl_xor_sync(0xffffffffu, snd, 8);
            float kp = (lane & 8) ? acc[j + 8] : acc[j];
            a8[j] = kp + r;
        }
        float a4[4];
#pragma unroll
        for (int j = 0; j < 4; j++) {
            float snd = (lane & 4) ? a8[j] : a8[j + 4];
            float r = __shfl_xor_sync(0xffffffffu, snd, 4);
            float kp = (lane & 4) ? a8[j + 4] : a8[j];
            a4[j] = kp + r;
        }
        float a2[2];
#pragma unroll
        for (int j = 0; j < 2; j++) {
            float snd = (lane & 2) ? a4[j] : a4[j + 2];
            float r = __shfl_xor_sync(0xffffffffu, snd, 2);
            float kp = (lane & 2) ? a4[j + 2] : a4[j];
            a2[j] = kp + r;
        }
        float snd1 = (lane & 1) ? a2[0] : a2[1];
        float r1 = __shfl_xor_sync(0xffffffffu, snd1, 1);
        float kp1 = (lane & 1) ? a2[1] : a2[0];
        float a1 = kp1 + r1;   // lane owns output (lane & 15)

        float es = a1 * sas_own;
        float ed = a1 * sad_own;
#pragma unroll
        for (int off = 8; off >= 1; off >>= 1) {
            es += __shfl_xor_sync(0xffffffffu, es, off);
            ed += __shfl_xor_sync(0xffffffffu, ed, off);
        }
        float wself = __expf(lrelu(es + ed));

        if (lane < 16) {
            d_hf2h[n * NC + oidx] = __float2half(a1);
            d_o2h[n * NC + oidx] = __float2half(wself * a1);
        }
        if (lane == 0) {
            d_e2[n] = pack_esed(es, ed);
            d_z2[n] = wself;
        }
    }
}

// ------- GAT2 aggregate: thread per edge, two v4 reds cover the node row -------
__global__ void gat2_aggr(const int* __restrict__ ei) {
    int e = blockIdx.x * blockDim.x + threadIdx.x;
    if (e >= EE) return;
    int s = ei[e];
    int d = ei[EE + e];
    unsigned int ps = __ldg(&d_e2[s]);
    unsigned int pd = __ldg(&d_e2[d]);
    float es = __low2float(*(const __half2*)&ps);
    float ed = __high2float(*(const __half2*)&pd);
    float w = __expf(lrelu(es + ed));
    const uint4* hf = (const uint4*)d_hf2h;
    uint4 a = __ldg(&hf[s * 2]);
    uint4 b = __ldg(&hf[s * 2 + 1]);
    __half2 ww = __float2half2_rn(w);
    __half* base = &d_o2h[d * NC];
    red_add_v4_f16x2(base,
                     hmul2_u(a.x, ww), hmul2_u(a.y, ww),
                     hmul2_u(a.z, ww), hmul2_u(a.w, ww));
    red_add_v4_f16x2(base + 8,
                     hmul2_u(b.x, ww), hmul2_u(b.y, ww),
                     hmul2_u(b.z, ww), hmul2_u(b.w, ww));
    atomicAdd(&d_z2[d], w);
}

// ------- normalize + bias + log_softmax (16 threads per node), fp32 output -------
__global__ void finish_logsoftmax(float* __restrict__ out, const float* __restrict__ g2b) {
    int gid = blockIdx.x * blockDim.x + threadIdx.x;
    int n = gid >> 4;
    int l = gid & 15;
    if (n >= NN) return;
    float zinv = 1.f / (d_z2[n] + 1e-16f);
    float v = __half2float(d_o2h[n * NC + l]) * zinv + __ldg(&g2b[l]);
    float m = v;
#pragma unroll
    for (int off = 8; off >= 1; off >>= 1)
        m = fmaxf(m, __shfl_xor_sync(0xffffffffu, m, off));
    float e = __expf(v - m);
    float ssum = e;
#pragma unroll
    for (int off = 8; off >= 1; off >>= 1)
        ssum += __shfl_xor_sync(0xffffffffu, ssum, off);
    out[n * NC + l] = v - m - __logf(ssum);
}

extern "C" void kernel_launch(void* const* d_in, const int* in_sizes, int n_in,
                              void* d_out, int out_size) {
    const float* x    = (const float*)d_in[0];
    const int*   ei   = (const int*)d_in[1];     // int32 (JAX x64 disabled)
    const float* ea   = (const float*)d_in[2];
    const float* w1   = (const float*)d_in[3];
    const float* b1   = (const float*)d_in[4];
    const float* w2   = (const float*)d_in[5];
    const float* b2   = (const float*)d_in[6];
    const float* root = (const float*)d_in[7];
    const float* nnb  = (const float*)d_in[8];
    const float* g1W  = (const float*)d_in[9];
    const float* g1as = (const float*)d_in[10];
    const float* g1ad = (const float*)d_in[11];
    const float* g1b  = (const float*)d_in[12];
    const float* g2W  = (const float*)d_in[13];
    const float* g2as = (const float*)d_in[14];
    const float* g2ad = (const float*)d_in[15];
    const float* g2b  = (const float*)d_in[16];
    float* out = (float*)d_out;

    // zero NNConv accumulators via graph-capturable memset nodes (not kernel launches)
    void* p_h0 = nullptr;
    void* p_cnt = nullptr;
    cudaGetSymbolAddress(&p_h0, d_h0);
    cudaGetSymbolAddress(&p_cnt, d_cnt);
    cudaMemsetAsync(p_h0, 0, (size_t)NN * HID * sizeof(float), 0);
    cudaMemsetAsync(p_cnt, 0, (size_t)NN * sizeof(float), 0);

    const int TB = 256;
    nnconv_edge<<<(EE + TB - 1) / TB, TB>>>(x, ei, ea, w1, b1, w2, b2);        // launch 1
    gat1_feat<<<(NN * 32 + TB - 1) / TB, TB>>>(x, root, nnb, g1W, g1as, g1ad); // launch 2
    gat1_aggr<<<(int)(((long long)EE * 8 + TB - 1) / TB), TB>>>(ei);           // launch 3
    gat2_feat<<<1024, TB>>>(g1b, g2W, g2as, g2ad);                             // launch 4 -> profiled
    gat2_aggr<<<(EE + TB - 1) / TB, TB>>>(ei);                                 // launch 5
    finish_logsoftmax<<<(NN * 16 + TB - 1) / TB, TB>>>(out, g2b);              // launch 6
}

// round 13
// speedup vs baseline: 2.2142x; 1.2904x over previous
#include <cuda_runtime.h>
#include <cuda_fp16.h>
#include <math.h>

// Problem constants
#define NN 100000      // nodes
#define EE 800000      // directed edges
#define EF 16
#define HID 8
#define H1 8
#define C1 16
#define F1 (H1 * C1)   // 128
#define NC 16

// ---------------- scratch (device globals; no allocation allowed) -------------
__device__ __align__(16) float d_h0[NN * HID];        // NNConv accum
__device__ __align__(16) float d_cnt[NN];             // in-degree
__device__ __align__(32) __half d_hf1h[NN * F1];      // GAT1 features, fp16
__device__ __align__(16) unsigned int d_e1[NN * H1];  // packed half2(es,ed) per head
__device__ __align__(16) float d_z1[NN * H1];         // GAT1 denom (init = self-loop)
__device__ __align__(32) __half d_o1h[NN * F1];       // GAT1 numerator, fp16 (v4 red target)
__device__ __align__(32) __half d_hf2h[NN * NC];      // GAT2 transformed features, fp16
__device__ __align__(16) unsigned int d_e2[NN];       // packed half2(es,ed)
__device__ __align__(16) float d_z2[NN];              // GAT2 denom (init = self-loop)
__device__ __align__(32) __half d_o2h[NN * NC];       // GAT2 numerator, fp16 (v4 red target)

__device__ __forceinline__ float lrelu(float v) { return v > 0.f ? v : 0.2f * v; }

// one-instruction 16-byte fp16 reduction (sm_90+)
__device__ __forceinline__ void red_add_v4_f16x2(__half* addr,
                                                 unsigned int r0, unsigned int r1,
                                                 unsigned int r2, unsigned int r3) {
    asm volatile("red.global.add.noftz.v4.f16x2 [%0], {%1,%2,%3,%4};"
        :: "l"(addr), "r"(r0), "r"(r1), "r"(r2), "r"(r3)
        : "memory");
}

__device__ __forceinline__ unsigned int hmul2_u(unsigned int u, __half2 ww) {
    __half2 h = *(__half2*)&u;
    h = __hmul2(h, ww);
    return *(unsigned int*)&h;
}

__device__ __forceinline__ unsigned int pack_esed(float es, float ed) {
    __half2 h = __floats2half2_rn(es, ed);
    return *(const unsigned int*)&h;
}

// ---------------- NNConv edge pass: edge MLP + scatter ----------------
__global__ void nnconv_edge(const float* __restrict__ x,
                            const int* __restrict__ ei,
                            const float* __restrict__ ea,
                            const float* __restrict__ w1, const float* __restrict__ b1,
                            const float* __restrict__ w2, const float* __restrict__ b2) {
    __shared__ float sw1[EF * HID];
    __shared__ float sw2[HID * HID];
    __shared__ float sb1[HID];
    __shared__ float sb2[HID];
    int t = threadIdx.x;
    if (t < EF * HID) sw1[t] = w1[t];
    if (t < HID * HID) sw2[t] = w2[t];
    if (t < HID) { sb1[t] = b1[t]; sb2[t] = b2[t]; }
    __syncthreads();

    int e = blockIdx.x * blockDim.x + t;
    if (e >= EE) return;
    int s = ei[e];
    int d = ei[EE + e];

    float a[EF];
    const float4* ea4 = (const float4*)(ea) + e * 4;
#pragma unroll
    for (int j = 0; j < 4; j++) {
        float4 v = ea4[j];
        a[j * 4 + 0] = v.x; a[j * 4 + 1] = v.y; a[j * 4 + 2] = v.z; a[j * 4 + 3] = v.w;
    }

    float hm[HID];
#pragma unroll
    for (int k = 0; k < HID; k++) {
        float acc = sb1[k];
#pragma unroll
        for (int i = 0; i < EF; i++) acc = fmaf(a[i], sw1[i * HID + k], acc);
        hm[k] = fmaxf(acc, 0.f);
    }

    float xs = __ldg(&x[s]);
    float we[HID];
#pragma unroll
    for (int o = 0; o < HID; o++) {
        float acc = sb2[o];
#pragma unroll
        for (int k = 0; k < HID; k++) acc = fmaf(hm[k], sw2[k * HID + o], acc);
        we[o] = xs * acc;
    }
    float4* dst4 = (float4*)(&d_h0[d * HID]);
    atomicAdd(dst4 + 0, make_float4(we[0], we[1], we[2], we[3]));
    atomicAdd(dst4 + 1, make_float4(we[4], we[5], we[6], we[7]));
    atomicAdd(&d_cnt[d], 1.0f);
}

// ---- fused: NNConv node epilogue + GAT1 transform + self-loop init (warp/node) ----
__global__ void gat1_feat(const float* __restrict__ x,
                          const float* __restrict__ root,
                          const float* __restrict__ nnb,
                          const float* __restrict__ g1W,
                          const float* __restrict__ g1as,
                          const float* __restrict__ g1ad) {
    int gid = blockIdx.x * blockDim.x + threadIdx.x;
    int n = gid >> 5;
    int lane = gid & 31;
    if (n >= NN) return;
    int k8 = lane & 7;

    float inv = 1.f / fmaxf(d_cnt[n], 1.f);
    float xr = __ldg(&x[n]);
    float hv = d_h0[n * HID + k8] * inv + xr * __ldg(&root[k8]) + __ldg(&nnb[k8]);
    hv = fmaxf(hv, 0.f);
    float h[HID];
#pragma unroll
    for (int k = 0; k < HID; k++) h[k] = __shfl_sync(0xffffffffu, hv, k);

    const float4* W4 = (const float4*)g1W;  // [8][32] float4
    float4 acc = make_float4(0.f, 0.f, 0.f, 0.f);
#pragma unroll
    for (int k = 0; k < HID; k++) {
        float4 w = __ldg(&W4[k * 32 + lane]);
        acc.x = fmaf(h[k], w.x, acc.x);
        acc.y = fmaf(h[k], w.y, acc.y);
        acc.z = fmaf(h[k], w.z, acc.z);
        acc.w = fmaf(h[k], w.w, acc.w);
    }
    {
        __half2 lo = __floats2half2_rn(acc.x, acc.y);
        __half2 hi = __floats2half2_rn(acc.z, acc.w);
        uint2 p;
        p.x = *(const unsigned int*)&lo;
        p.y = *(const unsigned int*)&hi;
        ((uint2*)d_hf1h)[n * 32 + lane] = p;
    }

    float4 as4 = __ldg(&((const float4*)g1as)[lane]);
    float4 ad4 = __ldg(&((const float4*)g1ad)[lane]);
    float es = acc.x * as4.x + acc.y * as4.y + acc.z * as4.z + acc.w * as4.w;
    float ed = acc.x * ad4.x + acc.y * ad4.y + acc.z * ad4.z + acc.w * ad4.w;
    es += __shfl_xor_sync(0xffffffffu, es, 1);
    es += __shfl_xor_sync(0xffffffffu, es, 2);
    ed += __shfl_xor_sync(0xffffffffu, ed, 1);
    ed += __shfl_xor_sync(0xffffffffu, ed, 2);

    float wself = __expf(lrelu(es + ed));
    {
        __half2 lo = __floats2half2_rn(wself * acc.x, wself * acc.y);
        __half2 hi = __floats2half2_rn(wself * acc.z, wself * acc.w);
        uint2 p;
        p.x = *(const unsigned int*)&lo;
        p.y = *(const unsigned int*)&hi;
        ((uint2*)d_o1h)[n * 32 + lane] = p;
    }
    if ((lane & 3) == 0) {
        int hh = lane >> 2;
        d_e1[n * H1 + hh] = pack_esed(es, ed);
        d_z1[n * H1 + hh] = wself;
    }
}

// ------- GAT1 aggregate: 8 lanes/edge (one head each), two v4 reds per lane -------
__global__ void gat1_aggr(const int* __restrict__ ei) {
    long long gtid = (long long)blockIdx.x * blockDim.x + threadIdx.x;
    int e = (int)(gtid >> 3);
    int hh = (int)(gtid & 7);
    if (e >= EE) return;
    int s = __ldg(&ei[e]);
    int d = __ldg(&ei[EE + e]);

    unsigned int ps = __ldg(&d_e1[s * H1 + hh]);
    unsigned int pd = __ldg(&d_e1[d * H1 + hh]);
    float es = __low2float(*(const __half2*)&ps);
    float ed = __high2float(*(const __half2*)&pd);
    float w = __expf(lrelu(es + ed));

    const uint4* hf = (const uint4*)d_hf1h;     // 8 halves per uint4
    uint4 a = __ldg(&hf[s * 16 + hh * 2]);
    uint4 b = __ldg(&hf[s * 16 + hh * 2 + 1]);
    __half2 ww = __float2half2_rn(w);

    __half* base = &d_o1h[d * F1 + hh * 16];
    red_add_v4_f16x2(base,
                     hmul2_u(a.x, ww), hmul2_u(a.y, ww),
                     hmul2_u(a.z, ww), hmul2_u(a.w, ww));
    red_add_v4_f16x2(base + 8,
                     hmul2_u(b.x, ww), hmul2_u(b.y, ww),
                     hmul2_u(b.z, ww), hmul2_u(b.w, ww));
    atomicAdd(&d_z1[d * H1 + hh], w);
}

// ---- gat2_feat v3: block-tiled shared-memory GEMV, 16 nodes per tile ----
// Phase 1: coalesced normalize+bias+ELU into shared sv[16][132].
// Phase 2: thread = (node, col) computes a 128-dot from shared; no cross-lane
//          reduction in the dot. Only es/ed uses a 4-level 16-lane shfl.
#define KP 132   // padded row length (floats) to dodge bank conflicts
__global__ void gat2_feat(const float* __restrict__ g1b,
                          const float* __restrict__ g2W,
                          const float* __restrict__ g2as,
                          const float* __restrict__ g2ad) {
    __shared__ float swT[NC * KP];   // [col][k], transposed W2
    __shared__ float sv[16 * KP];    // [node][k]
    __shared__ float sb[F1];
    __shared__ float sas[NC], sad[NC];
    int tid = threadIdx.x;

    // one-time block setup: transpose W2 into shared
    for (int i = tid; i < F1 * NC; i += 256) {
        int k = i >> 4, c = i & 15;
        swT[c * KP + k] = __ldg(&g2W[i]);
    }
    if (tid < F1) sb[tid] = __ldg(&g1b[tid]);
    if (tid < NC) { sas[tid] = __ldg(&g2as[tid]); sad[tid] = __ldg(&g2ad[tid]); }
    __syncthreads();

    const unsigned int* o1u = (const unsigned int*)d_o1h;   // half2 words
    int node16_p2 = tid >> 4;        // phase-2 node within tile
    int col = tid & 15;              // phase-2 output column
    float sas_own = sas[col];
    float sad_own = sad[col];

    for (int ng = blockIdx.x; ng < NN / 16; ng += gridDim.x) {
        int nb = ng * 16;
        // ---- phase 1: 1024 half2-words, 4 per thread, coalesced ----
#pragma unroll
        for (int j = 0; j < 4; j++) {
            int idx = tid + 256 * j;        // 0..1023
            int nd = idx >> 6;              // node within tile
            int up = idx & 63;              // half2 index within row
            int c = up * 2;
            int n = nb + nd;
            unsigned int p = __ldg(&o1u[(size_t)n * 64 + up]);
            float zinv = 1.f / (d_z1[n * H1 + (c >> 4)] + 1e-16f);
            float2 f = __half22float2(*(const __half2*)&p);
            float v0 = f.x * zinv + sb[c];
            float v1 = f.y * zinv + sb[c + 1];
            v0 = v0 > 0.f ? v0 : (__expf(v0) - 1.f);
            v1 = v1 > 0.f ? v1 : (__expf(v1) - 1.f);
            *(float2*)(&sv[nd * KP + c]) = make_float2(v0, v1);
        }
        __syncthreads();

        // ---- phase 2: one thread per (node, col) ----
        {
            const float4* wrow = (const float4*)(&swT[col * KP]);
            const float4* vrow = (const float4*)(&sv[node16_p2 * KP]);
            float acc = 0.f;
#pragma unroll
            for (int k4 = 0; k4 < 32; k4++) {
                float4 w = wrow[k4];
                float4 v = vrow[k4];
                acc += w.x * v.x + w.y * v.y + w.z * v.z + w.w * v.w;
            }
            int n = nb + node16_p2;
            float es = acc * sas_own;
            float ed = acc * sad_own;
#pragma unroll
            for (int off = 8; off >= 1; off >>= 1) {
                es += __shfl_xor_sync(0xffffffffu, es, off);
                ed += __shfl_xor_sync(0xffffffffu, ed, off);
            }
            float wself = __expf(lrelu(es + ed));
            d_hf2h[n * NC + col] = __float2half(acc);
            d_o2h[n * NC + col] = __float2half(wself * acc);
            if (col == 0) {
                d_e2[n] = pack_esed(es, ed);
                d_z2[n] = wself;
            }
        }
        __syncthreads();   // sv reused next iteration
    }
}

// ------- GAT2 aggregate: thread per edge, two v4 reds cover the node row -------
__global__ void gat2_aggr(const int* __restrict__ ei) {
    int e = blockIdx.x * blockDim.x + threadIdx.x;
    if (e >= EE) return;
    int s = ei[e];
    int d = ei[EE + e];
    unsigned int ps = __ldg(&d_e2[s]);
    unsigned int pd = __ldg(&d_e2[d]);
    float es = __low2float(*(const __half2*)&ps);
    float ed = __high2float(*(const __half2*)&pd);
    float w = __expf(lrelu(es + ed));
    const uint4* hf = (const uint4*)d_hf2h;
    uint4 a = __ldg(&hf[s * 2]);
    uint4 b = __ldg(&hf[s * 2 + 1]);
    __half2 ww = __float2half2_rn(w);
    __half* base = &d_o2h[d * NC];
    red_add_v4_f16x2(base,
                     hmul2_u(a.x, ww), hmul2_u(a.y, ww),
                     hmul2_u(a.z, ww), hmul2_u(a.w, ww));
    red_add_v4_f16x2(base + 8,
                     hmul2_u(b.x, ww), hmul2_u(b.y, ww),
                     hmul2_u(b.z, ww), hmul2_u(b.w, ww));
    atomicAdd(&d_z2[d], w);
}

// ------- normalize + bias + log_softmax (16 threads per node), fp32 output -------
__global__ void finish_logsoftmax(float* __restrict__ out, const float* __restrict__ g2b) {
    int gid = blockIdx.x * blockDim.x + threadIdx.x;
    int n = gid >> 4;
    int l = gid & 15;
    if (n >= NN) return;
    float zinv = 1.f / (d_z2[n] + 1e-16f);
    float v = __half2float(d_o2h[n * NC + l]) * zinv + __ldg(&g2b[l]);
    float m = v;
#pragma unroll
    for (int off = 8; off >= 1; off >>= 1)
        m = fmaxf(m, __shfl_xor_sync(0xffffffffu, m, off));
    float e = __expf(v - m);
    float ssum = e;
#pragma unroll
    for (int off = 8; off >= 1; off >>= 1)
        ssum += __shfl_xor_sync(0xffffffffu, ssum, off);
    out[n * NC + l] = v - m - __logf(ssum);
}

extern "C" void kernel_launch(void* const* d_in, const int* in_sizes, int n_in,
                              void* d_out, int out_size) {
    const float* x    = (const float*)d_in[0];
    const int*   ei   = (const int*)d_in[1];     // int32 (JAX x64 disabled)
    const float* ea   = (const float*)d_in[2];
    const float* w1   = (const float*)d_in[3];
    const float* b1   = (const float*)d_in[4];
    const float* w2   = (const float*)d_in[5];
    const float* b2   = (const float*)d_in[6];
    const float* root = (const float*)d_in[7];
    const float* nnb  = (const float*)d_in[8];
    const float* g1W  = (const float*)d_in[9];
    const float* g1as = (const float*)d_in[10];
    const float* g1ad = (const float*)d_in[11];
    const float* g1b  = (const float*)d_in[12];
    const float* g2W  = (const float*)d_in[13];
    const float* g2as = (const float*)d_in[14];
    const float* g2ad = (const float*)d_in[15];
    const float* g2b  = (const float*)d_in[16];
    float* out = (float*)d_out;

    // zero NNConv accumulators via graph-capturable memset nodes
    void* p_h0 = nullptr;
    void* p_cnt = nullptr;
    cudaGetSymbolAddress(&p_h0, d_h0);
    cudaGetSymbolAddress(&p_cnt, d_cnt);
    cudaMemsetAsync(p_h0, 0, (size_t)NN * HID * sizeof(float), 0);
    cudaMemsetAsync(p_cnt, 0, (size_t)NN * sizeof(float), 0);

    const int TB = 256;
    nnconv_edge<<<(EE + TB - 1) / TB, TB>>>(x, ei, ea, w1, b1, w2, b2);        // launch 1
    gat1_feat<<<(NN * 32 + TB - 1) / TB, TB>>>(x, root, nnb, g1W, g1as, g1ad); // launch 2
    gat1_aggr<<<(int)(((long long)EE * 8 + TB - 1) / TB), TB>>>(ei);           // launch 3
    gat2_feat<<<2048, TB>>>(g1b, g2W, g2as, g2ad);                             // launch 4 -> profiled
    gat2_aggr<<<(EE + TB - 1) / TB, TB>>>(ei);                                 // launch 5
    finish_logsoftmax<<<(NN * 16 + TB - 1) / TB, TB>>>(out, g2b);              // launch 6
}

// round 17
// speedup vs baseline: 2.2493x; 1.0159x over previous
#include <cuda_runtime.h>
#include <cuda_fp16.h>
#include <math.h>

// Problem constants
#define NN 100000      // nodes
#define EE 800000      // directed edges
#define EF 16
#define HID 8
#define H1 8
#define C1 16
#define F1 (H1 * C1)   // 128
#define NC 16

// ---------------- scratch (device globals; no allocation allowed) -------------
__device__ __align__(16) float d_h0[NN * HID];        // NNConv accum
__device__ __align__(16) float d_cnt[NN];             // in-degree
__device__ __align__(32) __half d_hf1h[NN * F1];      // GAT1 features, fp16
__device__ __align__(16) unsigned int d_e1[NN * H1];  // packed half2(es,ed) per head
__device__ __align__(16) float d_z1[NN * H1];         // GAT1 denom (init = self-loop)
__device__ __align__(32) __half d_o1h[NN * F1];       // GAT1 numerator, fp16 (v4 red target)
__device__ __align__(32) __half d_hf2h[NN * NC];      // GAT2 transformed features, fp16
__device__ __align__(16) unsigned int d_e2[NN];       // packed half2(es,ed)
__device__ __align__(16) float d_z2[NN];              // GAT2 denom (init = self-loop)
__device__ __align__(32) __half d_o2h[NN * NC];       // GAT2 numerator, fp16 (v4 red target)

__device__ __forceinline__ float lrelu(float v) { return v > 0.f ? v : 0.2f * v; }

// one-instruction 16-byte fp16 reduction (sm_90+)
__device__ __forceinline__ void red_add_v4_f16x2(__half* addr,
                                                 unsigned int r0, unsigned int r1,
                                                 unsigned int r2, unsigned int r3) {
    asm volatile("red.global.add.noftz.v4.f16x2 [%0], {%1,%2,%3,%4};"
        :: "l"(addr), "r"(r0), "r"(r1), "r"(r2), "r"(r3)
        : "memory");
}

__device__ __forceinline__ unsigned int hmul2_u(unsigned int u, __half2 ww) {
    __half2 h = *(__half2*)&u;
    h = __hmul2(h, ww);
    return *(unsigned int*)&h;
}

__device__ __forceinline__ unsigned int pack_esed(float es, float ed) {
    __half2 h = __floats2half2_rn(es, ed);
    return *(const unsigned int*)&h;
}

// accumulate fp16 product pair into fp32
__device__ __forceinline__ float acc_h2(unsigned int wu, unsigned int vu) {
    __half2 p = __hmul2(*(const __half2*)&wu, *(const __half2*)&vu);
    float2 f = __half22float2(p);
    return f.x + f.y;
}

// ---------------- NNConv edge pass: edge MLP + scatter ----------------
__global__ void nnconv_edge(const float* __restrict__ x,
                            const int* __restrict__ ei,
                            const float* __restrict__ ea,
                            const float* __restrict__ w1, const float* __restrict__ b1,
                            const float* __restrict__ w2, const float* __restrict__ b2) {
    __shared__ float sw1[EF * HID];
    __shared__ float sw2[HID * HID];
    __shared__ float sb1[HID];
    __shared__ float sb2[HID];
    int t = threadIdx.x;
    if (t < EF * HID) sw1[t] = w1[t];
    if (t < HID * HID) sw2[t] = w2[t];
    if (t < HID) { sb1[t] = b1[t]; sb2[t] = b2[t]; }
    __syncthreads();

    int e = blockIdx.x * blockDim.x + t;
    if (e >= EE) return;
    int s = ei[e];
    int d = ei[EE + e];

    float a[EF];
    const float4* ea4 = (const float4*)(ea) + e * 4;
#pragma unroll
    for (int j = 0; j < 4; j++) {
        float4 v = ea4[j];
        a[j * 4 + 0] = v.x; a[j * 4 + 1] = v.y; a[j * 4 + 2] = v.z; a[j * 4 + 3] = v.w;
    }

    float hm[HID];
#pragma unroll
    for (int k = 0; k < HID; k++) {
        float acc = sb1[k];
#pragma unroll
        for (int i = 0; i < EF; i++) acc = fmaf(a[i], sw1[i * HID + k], acc);
        hm[k] = fmaxf(acc, 0.f);
    }

    float xs = __ldg(&x[s]);
    float we[HID];
#pragma unroll
    for (int o = 0; o < HID; o++) {
        float acc = sb2[o];
#pragma unroll
        for (int k = 0; k < HID; k++) acc = fmaf(hm[k], sw2[k * HID + o], acc);
        we[o] = xs * acc;
    }
    float4* dst4 = (float4*)(&d_h0[d * HID]);
    atomicAdd(dst4 + 0, make_float4(we[0], we[1], we[2], we[3]));
    atomicAdd(dst4 + 1, make_float4(we[4], we[5], we[6], we[7]));
    atomicAdd(&d_cnt[d], 1.0f);
}

// ---- fused: NNConv node epilogue + GAT1 transform + self-loop init (warp/node) ----
__global__ void gat1_feat(const float* __restrict__ x,
                          const float* __restrict__ root,
                          const float* __restrict__ nnb,
                          const float* __restrict__ g1W,
                          const float* __restrict__ g1as,
                          const float* __restrict__ g1ad) {
    int gid = blockIdx.x * blockDim.x + threadIdx.x;
    int n = gid >> 5;
    int lane = gid & 31;
    if (n >= NN) return;
    int k8 = lane & 7;

    float inv = 1.f / fmaxf(d_cnt[n], 1.f);
    float xr = __ldg(&x[n]);
    float hv = d_h0[n * HID + k8] * inv + xr * __ldg(&root[k8]) + __ldg(&nnb[k8]);
    hv = fmaxf(hv, 0.f);
    float h[HID];
#pragma unroll
    for (int k = 0; k < HID; k++) h[k] = __shfl_sync(0xffffffffu, hv, k);

    const float4* W4 = (const float4*)g1W;  // [8][32] float4
    float4 acc = make_float4(0.f, 0.f, 0.f, 0.f);
#pragma unroll
    for (int k = 0; k < HID; k++) {
        float4 w = __ldg(&W4[k * 32 + lane]);
        acc.x = fmaf(h[k], w.x, acc.x);
        acc.y = fmaf(h[k], w.y, acc.y);
        acc.z = fmaf(h[k], w.z, acc.z);
        acc.w = fmaf(h[k], w.w, acc.w);
    }
    {
        __half2 lo = __floats2half2_rn(acc.x, acc.y);
        __half2 hi = __floats2half2_rn(acc.z, acc.w);
        uint2 p;
        p.x = *(const unsigned int*)&lo;
        p.y = *(const unsigned int*)&hi;
        ((uint2*)d_hf1h)[n * 32 + lane] = p;
    }

    float4 as4 = __ldg(&((const float4*)g1as)[lane]);
    float4 ad4 = __ldg(&((const float4*)g1ad)[lane]);
    float es = acc.x * as4.x + acc.y * as4.y + acc.z * as4.z + acc.w * as4.w;
    float ed = acc.x * ad4.x + acc.y * ad4.y + acc.z * ad4.z + acc.w * ad4.w;
    es += __shfl_xor_sync(0xffffffffu, es, 1);
    es += __shfl_xor_sync(0xffffffffu, es, 2);
    ed += __shfl_xor_sync(0xffffffffu, ed, 1);
    ed += __shfl_xor_sync(0xffffffffu, ed, 2);

    float wself = __expf(lrelu(es + ed));
    {
        __half2 lo = __floats2half2_rn(wself * acc.x, wself * acc.y);
        __half2 hi = __floats2half2_rn(wself * acc.z, wself * acc.w);
        uint2 p;
        p.x = *(const unsigned int*)&lo;
        p.y = *(const unsigned int*)&hi;
        ((uint2*)d_o1h)[n * 32 + lane] = p;
    }
    if ((lane & 3) == 0) {
        int hh = lane >> 2;
        d_e1[n * H1 + hh] = pack_esed(es, ed);
        d_z1[n * H1 + hh] = wself;
    }
}

// ------- GAT1 aggregate: 8 lanes/edge (one head each), two v4 reds per lane -------
__global__ void gat1_aggr(const int* __restrict__ ei) {
    long long gtid = (long long)blockIdx.x * blockDim.x + threadIdx.x;
    int e = (int)(gtid >> 3);
    int hh = (int)(gtid & 7);
    if (e >= EE) return;
    int s = __ldg(&ei[e]);
    int d = __ldg(&ei[EE + e]);

    unsigned int ps = __ldg(&d_e1[s * H1 + hh]);
    unsigned int pd = __ldg(&d_e1[d * H1 + hh]);
    float es = __low2float(*(const __half2*)&ps);
    float ed = __high2float(*(const __half2*)&pd);
    float w = __expf(lrelu(es + ed));

    const uint4* hf = (const uint4*)d_hf1h;     // 8 halves per uint4
    uint4 a = __ldg(&hf[s * 16 + hh * 2]);
    uint4 b = __ldg(&hf[s * 16 + hh * 2 + 1]);
    __half2 ww = __float2half2_rn(w);

    __half* base = &d_o1h[d * F1 + hh * 16];
    red_add_v4_f16x2(base,
                     hmul2_u(a.x, ww), hmul2_u(a.y, ww),
                     hmul2_u(a.z, ww), hmul2_u(a.w, ww));
    red_add_v4_f16x2(base + 8,
                     hmul2_u(b.x, ww), hmul2_u(b.y, ww),
                     hmul2_u(b.z, ww), hmul2_u(b.w, ww));
    atomicAdd(&d_z1[d * H1 + hh], w);
}

// ---- gat2_feat v4: fp16 shared tiles + 2-col blocking; 32 nodes/tile ----
// Phase 1: coalesced normalize+bias+ELU -> sv_h[32][KPH] (fp16).
// Phase 2: thread = (node, col-pair): two 128-dots from fp16 shared,
//          fp32 accumulation; es/ed via 3-level shfl over 8 lanes.
#define KPH 136   // padded row length in halves (272B rows, 16B-aligned)
__global__ void gat2_feat(const float* __restrict__ g1b,
                          const float* __restrict__ g2W,
                          const float* __restrict__ g2as,
                          const float* __restrict__ g2ad) {
    __shared__ __half swT_h[NC * KPH];   // [col][k]
    __shared__ __half sv_h[32 * KPH];    // [node][k]
    __shared__ float sb[F1];
    __shared__ float sas[NC], sad[NC];
    int tid = threadIdx.x;

    for (int i = tid; i < F1 * NC; i += 256) {
        int k = i >> 4, c = i & 15;
        swT_h[c * KPH + k] = __float2half(__ldg(&g2W[i]));
    }
    if (tid < F1) sb[tid] = __ldg(&g1b[tid]);
    if (tid < NC) { sas[tid] = __ldg(&g2as[tid]); sad[tid] = __ldg(&g2ad[tid]); }
    __syncthreads();

    const unsigned int* o1u = (const unsigned int*)d_o1h;   // half2 words
    int node32 = tid >> 3;      // phase-2 node in tile (0..31)
    int cp = tid & 7;           // col pair (0..7)
    int c0 = cp * 2;
    float sas0 = sas[c0], sas1 = sas[c0 + 1];
    float sad0 = sad[c0], sad1 = sad[c0 + 1];

    for (int ng = blockIdx.x; ng < NN / 32; ng += gridDim.x) {
        int nb = ng * 32;
        // ---- phase 1: 2048 half2-words, 8 per thread, coalesced ----
#pragma unroll
        for (int j = 0; j < 8; j++) {
            int idx = tid + 256 * j;        // 0..2047
            int nd = idx >> 6;              // node within tile
            int up = idx & 63;              // half2 index within row
            int c = up * 2;
            int n = nb + nd;
            unsigned int p = __ldg(&o1u[(size_t)n * 64 + up]);
            float zinv = 1.f / (d_z1[n * H1 + (c >> 4)] + 1e-16f);
            float2 f = __half22float2(*(const __half2*)&p);
            float v0 = f.x * zinv + sb[c];
            float v1 = f.y * zinv + sb[c + 1];
            v0 = v0 > 0.f ? v0 : (__expf(v0) - 1.f);
            v1 = v1 > 0.f ? v1 : (__expf(v1) - 1.f);
            *(__half2*)(&sv_h[nd * KPH + c]) = __floats2half2_rn(v0, v1);
        }
        __syncthreads();

        // ---- phase 2: thread = (node, 2 cols) ----
        {
            const uint4* w0r = (const uint4*)(&swT_h[c0 * KPH]);
            const uint4* w1r = (const uint4*)(&swT_h[(c0 + 1) * KPH]);
            const uint4* vr = (const uint4*)(&sv_h[node32 * KPH]);
            float acc0 = 0.f, acc1 = 0.f;
#pragma unroll
            for (int k8 = 0; k8 < 16; k8++) {
                uint4 vv = vr[k8];
                uint4 wa = w0r[k8];
                uint4 wb = w1r[k8];
                acc0 += acc_h2(wa.x, vv.x) + acc_h2(wa.y, vv.y)
                      + acc_h2(wa.z, vv.z) + acc_h2(wa.w, vv.w);
                acc1 += acc_h2(wb.x, vv.x) + acc_h2(wb.y, vv.y)
                      + acc_h2(wb.z, vv.z) + acc_h2(wb.w, vv.w);
            }
            int n = nb + node32;
            float es = acc0 * sas0 + acc1 * sas1;
            float ed = acc0 * sad0 + acc1 * sad1;
#pragma unroll
            for (int off = 4; off >= 1; off >>= 1) {
                es += __shfl_xor_sync(0xffffffffu, es, off);
                ed += __shfl_xor_sync(0xffffffffu, ed, off);
            }
            float wself = __expf(lrelu(es + ed));
            *(__half2*)(&d_hf2h[n * NC + c0]) = __floats2half2_rn(acc0, acc1);
            *(__half2*)(&d_o2h[n * NC + c0]) = __floats2half2_rn(wself * acc0, wself * acc1);
            if (cp == 0) {
                d_e2[n] = pack_esed(es, ed);
                d_z2[n] = wself;
            }
        }
        __syncthreads();   // sv_h reused next iteration
    }
}

// ------- GAT2 aggregate: thread per edge, two v4 reds cover the node row -------
__global__ void gat2_aggr(const int* __restrict__ ei) {
    int e = blockIdx.x * blockDim.x + threadIdx.x;
    if (e >= EE) return;
    int s = ei[e];
    int d = ei[EE + e];
    unsigned int ps = __ldg(&d_e2[s]);
    unsigned int pd = __ldg(&d_e2[d]);
    float es = __low2float(*(const __half2*)&ps);
    float ed = __high2float(*(const __half2*)&pd);
    float w = __expf(lrelu(es + ed));
    const uint4* hf = (const uint4*)d_hf2h;
    uint4 a = __ldg(&hf[s * 2]);
    uint4 b = __ldg(&hf[s * 2 + 1]);
    __half2 ww = __float2half2_rn(w);
    __half* base = &d_o2h[d * NC];
    red_add_v4_f16x2(base,
                     hmul2_u(a.x, ww), hmul2_u(a.y, ww),
                     hmul2_u(a.z, ww), hmul2_u(a.w, ww));
    red_add_v4_f16x2(base + 8,
                     hmul2_u(b.x, ww), hmul2_u(b.y, ww),
                     hmul2_u(b.z, ww), hmul2_u(b.w, ww));
    atomicAdd(&d_z2[d], w);
}

// ------- normalize + bias + log_softmax (16 threads per node), fp32 output -------
__global__ void finish_logsoftmax(float* __restrict__ out, const float* __restrict__ g2b) {
    int gid = blockIdx.x * blockDim.x + threadIdx.x;
    int n = gid >> 4;
    int l = gid & 15;
    if (n >= NN) return;
    float zinv = 1.f / (d_z2[n] + 1e-16f);
    float v = __half2float(d_o2h[n * NC + l]) * zinv + __ldg(&g2b[l]);
    float m = v;
#pragma unroll
    for (int off = 8; off >= 1; off >>= 1)
        m = fmaxf(m, __shfl_xor_sync(0xffffffffu, m, off));
    float e = __expf(v - m);
    float ssum = e;
#pragma unroll
    for (int off = 8; off >= 1; off >>= 1)
        ssum += __shfl_xor_sync(0xffffffffu, ssum, off);
    out[n * NC + l] = v - m - __logf(ssum);
}

extern "C" void kernel_launch(void* const* d_in, const int* in_sizes, int n_in,
                              void* d_out, int out_size) {
    const float* x    = (const float*)d_in[0];
    const int*   ei   = (const int*)d_in[1];     // int32 (JAX x64 disabled)
    const float* ea   = (const float*)d_in[2];
    const float* w1   = (const float*)d_in[3];
    const float* b1   = (const float*)d_in[4];
    const float* w2   = (const float*)d_in[5];
    const float* b2   = (const float*)d_in[6];
    const float* root = (const float*)d_in[7];
    const float* nnb  = (const float*)d_in[8];
    const float* g1W  = (const float*)d_in[9];
    const float* g1as = (const float*)d_in[10];
    const float* g1ad = (const float*)d_in[11];
    const float* g1b  = (const float*)d_in[12];
    const float* g2W  = (const float*)d_in[13];
    const float* g2as = (const float*)d_in[14];
    const float* g2ad = (const float*)d_in[15];
    const float* g2b  = (const float*)d_in[16];
    float* out = (float*)d_out;

    // zero NNConv accumulators via graph-capturable memset nodes
    void* p_h0 = nullptr;
    void* p_cnt = nullptr;
    cudaGetSymbolAddress(&p_h0, d_h0);
    cudaGetSymbolAddress(&p_cnt, d_cnt);
    cudaMemsetAsync(p_h0, 0, (size_t)NN * HID * sizeof(float), 0);
    cudaMemsetAsync(p_cnt, 0, (size_t)NN * sizeof(float), 0);

    const int TB = 256;
    nnconv_edge<<<(EE + TB - 1) / TB, TB>>>(x, ei, ea, w1, b1, w2, b2);        // launch 1
    gat1_feat<<<(NN * 32 + TB - 1) / TB, TB>>>(x, root, nnb, g1W, g1as, g1ad); // launch 2
    gat1_aggr<<<(int)(((long long)EE * 8 + TB - 1) / TB), TB>>>(ei);           // launch 3
    gat2_feat<<<2048, TB>>>(g1b, g2W, g2as, g2ad);                             // launch 4 -> profiled
    gat2_aggr<<<(EE + TB - 1) / TB, TB>>>(ei);                                 // launch 5
    finish_logsoftmax<<<(NN * 16 + TB - 1) / TB, TB>>>(out, g2b);              // launch 6
}